// round 11
// baseline (speedup 1.0000x reference)
#include <cuda_runtime.h>
#include <cuda_bf16.h>
#include <cstdint>

#define B_ 256
#define S_ 512
#define E_ 512
#define H_ 1024
#define HH_ 512
#define MTOK (B_ * S_)

typedef __nv_bfloat16 bf16;

// ---------------- device-global scratch ------------------------------------
__device__ bf16 g_seqh[(size_t)MTOK * E_];
__device__ bf16 g_seql[(size_t)MTOK * E_];
__device__ bf16 g_tmph[(size_t)MTOK * HH_];
__device__ bf16 g_tmpl[(size_t)MTOK * HH_];
__device__ float g_xh[(size_t)MTOK * H_];
__device__ bf16 g_w1xTh[HH_ * E_], g_w1xTl[HH_ * E_];   // [N,K]
__device__ bf16 g_w2xTh[H_ * HH_], g_w2xTl[H_ * HH_];
__device__ bf16 g_w1hTh[HH_ * H_], g_w1hTl[HH_ * H_];
__device__ bf16 g_w2hTh[H_ * HH_], g_w2hTl[H_ * HH_];
__device__ bf16 g_hh[B_ * H_], g_hl[B_ * H_];
__device__ bf16 g_ih[2][B_ * HH_], g_il[2][B_ * HH_];   // inter double-buffered
// monotonic per-CTA flags (128B stride per flag)
__device__ volatile unsigned g_fh[8][16 * 32];
__device__ volatile unsigned g_fi[8][16 * 32];

// ---------------- helpers ----------------------------------------------------
__device__ __forceinline__ uint32_t smem_u32(const void* p) {
    uint32_t r;
    asm("{ .reg .u64 t; cvta.to.shared.u64 t, %1; cvt.u32.u64 %0, t; }" : "=r"(r) : "l"(p));
    return r;
}
__device__ __forceinline__ float fast_tanh(float x) {
    float y; asm("tanh.approx.f32 %0, %1;" : "=f"(y) : "f"(x)); return y;
}
__device__ __forceinline__ void hmma(float c[4], const uint32_t a[4], const uint32_t b[2]) {
    asm volatile("mma.sync.aligned.m16n8k16.row.col.f32.bf16.bf16.f32 "
        "{%0,%1,%2,%3}, {%4,%5,%6,%7}, {%8,%9}, {%0,%1,%2,%3};"
        : "+f"(c[0]), "+f"(c[1]), "+f"(c[2]), "+f"(c[3])
        : "r"(a[0]), "r"(a[1]), "r"(a[2]), "r"(a[3]), "r"(b[0]), "r"(b[1]));
}
// swizzled ldmatrix x4: A frag m16k16
__device__ __forceinline__ void ldsm4_s(uint32_t a[4], const bf16* tb, int rowlen,
                                        int rowbase, int ko, int lane) {
    int row = rowbase + (lane & 15);
    int seg = (ko >> 3) + (lane >> 4);
    uint32_t addr = smem_u32(tb + row * rowlen + ((seg ^ (row & 7)) << 3));
    asm volatile("ldmatrix.sync.aligned.m8n8.x4.shared.b16 {%0,%1,%2,%3}, [%4];"
        : "=r"(a[0]), "=r"(a[1]), "=r"(a[2]), "=r"(a[3]) : "r"(addr));
}
// fused x4: B frags hi (b[0..1]) + lo (b[2..3]) for one n8 row-block
__device__ __forceinline__ void ldsm4_bf(uint32_t b[4], const bf16* th, const bf16* tl,
                                         int rowlen, int rowbase, int ko, int lane) {
    const bf16* base = ((lane & 16) == 0) ? th : tl;
    int row = rowbase + (lane & 7);
    int seg = (ko >> 3) + ((lane >> 3) & 1);
    uint32_t addr = smem_u32(base + row * rowlen + ((seg ^ (row & 7)) << 3));
    asm volatile("ldmatrix.sync.aligned.m8n8.x4.shared.b16 {%0,%1,%2,%3}, [%4];"
        : "=r"(b[0]), "=r"(b[1]), "=r"(b[2]), "=r"(b[3]) : "r"(addr));
}
// fused x4: B frags for TWO adjacent n8 blocks (n16): b[0..1]=nf0, b[2..3]=nf1
__device__ __forceinline__ void ldsm4_n16(uint32_t b[4], const bf16* tb, int rowlen,
                                          int rowbase, int ko, int lane) {
    int row = rowbase + ((lane >> 4) << 3) + (lane & 7);
    int seg = (ko >> 3) + ((lane >> 3) & 1);
    uint32_t addr = smem_u32(tb + row * rowlen + ((seg ^ (row & 7)) << 3));
    asm volatile("ldmatrix.sync.aligned.m8n8.x4.shared.b16 {%0,%1,%2,%3}, [%4];"
        : "=r"(b[0]), "=r"(b[1]), "=r"(b[2]), "=r"(b[3]) : "r"(addr));
}
__device__ __forceinline__ void ldsm2_s(uint32_t b[2], const bf16* tb, int rowlen,
                                        int rowbase, int ko, int lane) {
    int row = rowbase + (lane & 7);
    int seg = (ko >> 3) + ((lane >> 3) & 1);
    uint32_t addr = smem_u32(tb + row * rowlen + ((seg ^ (row & 7)) << 3));
    asm volatile("ldmatrix.sync.aligned.m8n8.x2.shared.b16 {%0,%1}, [%2];"
        : "=r"(b[0]), "=r"(b[1]) : "r"(addr));
}
__device__ __forceinline__ void cp16(bf16* s, const bf16* g) {
    uint32_t sa = smem_u32(s);
    asm volatile("cp.async.cg.shared.global [%0], [%1], 16;" :: "r"(sa), "l"(g));
}
#define CP_COMMIT() asm volatile("cp.async.commit_group;" ::: "memory")
#define CP_WAIT(n) asm volatile("cp.async.wait_group %0;" :: "n"(n) : "memory")

// async-load [ROWS x SEGS*8] bf16 tile, swizzled
template <int ROWS, int SEGS>
__device__ __forceinline__ void ld_sw(bf16* dst, const bf16* __restrict__ src,
                                      size_t row0, int ld, int k0, int tid) {
#pragma unroll
    for (int i = tid; i < ROWS * SEGS; i += 256) {
        int r = i / SEGS, c = i % SEGS;
        cp16(dst + r * SEGS * 8 + ((c ^ (r & 7)) << 3),
             src + (row0 + (size_t)r) * (size_t)ld + k0 + c * 8);
    }
}

// warp-parallel acquire poll on cnt flags (cnt power of 2); all threads call
__device__ __forceinline__ void wait_flags(volatile unsigned* fl, int cnt,
                                           unsigned tgt, int lane) {
    const unsigned* p = (const unsigned*)(fl + (lane & (cnt - 1)) * 32);
    unsigned v;
    do {
        asm volatile("ld.acquire.gpu.u32 %0, [%1];" : "=r"(v) : "l"(p) : "memory");
    } while (__any_sync(0xffffffffu, (int)(v - tgt) < 0));
}
__device__ __forceinline__ void publish(volatile unsigned* fl, unsigned val) {
    __threadfence();
    asm volatile("st.release.gpu.u32 [%0], %1;" :: "l"((unsigned*)fl), "r"(val) : "memory");
}

// ---------------- prep kernels ----------------------------------------------
__global__ void split_kernel(const float* __restrict__ x, bf16* __restrict__ h,
                             bf16* __restrict__ l, size_t n) {
    size_t i = (size_t)blockIdx.x * 256 + threadIdx.x;
    if (i < n) {
        float v = x[i];
        bf16 a = __float2bfloat16(v);
        h[i] = a;
        l[i] = __float2bfloat16(v - __bfloat162float(a));
    }
}
__global__ void transpose_split(const float* __restrict__ W, bf16* __restrict__ Th,
                                bf16* __restrict__ Tl, int K, int N) {
    int idx = blockIdx.x * 256 + threadIdx.x;
    if (idx < N * K) {
        int n = idx / K, k = idx % K;
        float v = W[k * N + n];
        bf16 a = __float2bfloat16(v);
        Th[idx] = a;
        Tl[idx] = __float2bfloat16(v - __bfloat162float(a));
    }
}

// ---------------- phase-1 GEMM: out = act(A @ W^T + bias) -------------------
#define P1_AH 0
#define P1_AL 8192
#define P1_BH 16384
#define P1_BL 24576
#define P1_BUF 32768
#define P1_SMEM (2 * P1_BUF * 2)

__global__ __launch_bounds__(256) void ff_mma(
    const bf16* __restrict__ Ah, const bf16* __restrict__ Al,
    const bf16* __restrict__ Bh, const bf16* __restrict__ Bl,
    const float* __restrict__ bias, float* __restrict__ outF,
    bf16* __restrict__ outH, bf16* __restrict__ outL,
    int K, int N, int relu_split)
{
    extern __shared__ bf16 sm[];
    bf16* buf[2] = {sm, sm + P1_BUF};
    const int tid = threadIdx.x, lane = tid & 31, wid = tid >> 5;
    const int wm = wid & 3, wn = wid >> 2;
    const size_t rowBase = (size_t)blockIdx.y * 128;
    const int colBase = blockIdx.x * 128;
    const int nch = K / 64;

    float acc[2][8][4];
#pragma unroll
    for (int i = 0; i < 2; i++)
#pragma unroll
        for (int j = 0; j < 8; j++)
#pragma unroll
            for (int q = 0; q < 4; q++) acc[i][j][q] = 0.f;

    ld_sw<128, 8>(buf[0] + P1_AH, Ah, rowBase, K, 0, tid);
    ld_sw<128, 8>(buf[0] + P1_AL, Al, rowBase, K, 0, tid);
    ld_sw<128, 8>(buf[0] + P1_BH, Bh, (size_t)colBase, K, 0, tid);
    ld_sw<128, 8>(buf[0] + P1_BL, Bl, (size_t)colBase, K, 0, tid);
    CP_COMMIT();

    for (int kc = 0; kc < nch; kc++) {
        if (kc < nch - 1) {
            bf16* nb = buf[(kc + 1) & 1];
            int k0 = (kc + 1) * 64;
            ld_sw<128, 8>(nb + P1_AH, Ah, rowBase, K, k0, tid);
            ld_sw<128, 8>(nb + P1_AL, Al, rowBase, K, k0, tid);
            ld_sw<128, 8>(nb + P1_BH, Bh, (size_t)colBase, K, k0, tid);
            ld_sw<128, 8>(nb + P1_BL, Bl, (size_t)colBase, K, k0, tid);
            CP_COMMIT();
            CP_WAIT(1);
        } else {
            CP_WAIT(0);
        }
        __syncthreads();
        bf16* cb = buf[kc & 1];
#pragma unroll
        for (int ks = 0; ks < 4; ks++) {
            int ko = ks * 16;
            uint32_t ah[2][4], al[2][4];
#pragma unroll
            for (int mf = 0; mf < 2; mf++) {
                ldsm4_s(ah[mf], cb + P1_AH, 64, wm * 32 + mf * 16, ko, lane);
                ldsm4_s(al[mf], cb + P1_AL, 64, wm * 32 + mf * 16, ko, lane);
            }
#pragma unroll
            for (int nf = 0; nf < 8; nf++) {
                uint32_t bh[2], bl[2];
                ldsm2_s(bh, cb + P1_BH, 64, wn * 64 + nf * 8, ko, lane);
                ldsm2_s(bl, cb + P1_BL, 64, wn * 64 + nf * 8, ko, lane);
#pragma unroll
                for (int mf = 0; mf < 2; mf++) {
                    hmma(acc[mf][nf], ah[mf], bh);
                    hmma(acc[mf][nf], ah[mf], bl);
                    hmma(acc[mf][nf], al[mf], bh);
                }
            }
        }
        __syncthreads();
    }

#pragma unroll
    for (int mf = 0; mf < 2; mf++) {
#pragma unroll
        for (int nf = 0; nf < 8; nf++) {
            int cg = colBase + wn * 64 + nf * 8 + (lane & 3) * 2;
            float b0 = bias[cg], b1 = bias[cg + 1];
#pragma unroll
            for (int half = 0; half < 2; half++) {
                size_t rg = rowBase + wm * 32 + mf * 16 + (lane >> 2) + half * 8;
                float v0 = acc[mf][nf][half * 2] + b0;
                float v1 = acc[mf][nf][half * 2 + 1] + b1;
                if (relu_split) {
                    v0 = fmaxf(v0, 0.f);
                    v1 = fmaxf(v1, 0.f);
                    __nv_bfloat162 hv, lv;
                    hv.x = __float2bfloat16(v0);
                    hv.y = __float2bfloat16(v1);
                    lv.x = __float2bfloat16(v0 - __bfloat162float(hv.x));
                    lv.y = __float2bfloat16(v1 - __bfloat162float(hv.y));
                    *(__nv_bfloat162*)&outH[rg * N + cg] = hv;
                    *(__nv_bfloat162*)&outL[rg * N + cg] = lv;
                } else {
                    *(float2*)&outF[rg * N + cg] = make_float2(v0, v1);
                }
            }
        }
    }
}

// ---------------- persistent recurrence: 8 groups x 16 CTAs -----------------
// w1h slice resident (128 KB). Phase A: 6-stage deep h pipeline, single sync
// per chunk. Phase B: 2 stages (inter+w2h). Per-CTA flags as in R10.
#define RW_H 0
#define RW_L 32768
#define RD 65536
#define PB_AH 0
#define PB_AL 4096
#define PB_WH 8192
#define PB_WL 16384
#define PB_STAGE 24576
#define PA_STAGE 8192
#define R_SMEM ((65536 + 2 * 24576) * 2)

__global__ __launch_bounds__(256) void recurrence(
    const float* __restrict__ b1h, const float* __restrict__ b2h,
    const int* __restrict__ lens, float* __restrict__ out)
{
    extern __shared__ bf16 sm[];
    bf16* smWH = sm + RW_H;
    bf16* smWL = sm + RW_L;
    const int tid = threadIdx.x, lane = tid & 31, wid = tid >> 5;
    const int wm = wid & 1, wn = wid >> 1;  // 2m x 4n warps
    const int cta = blockIdx.x;
    const int grp = cta >> 4;
    const int slot = cta & 15;
    const size_t rbase = (size_t)grp * 32;
    const int cbaseA = slot * 32;
    const int cbaseB = slot * 64;

    const unsigned baseH = g_fh[grp][slot * 32];
    const unsigned baseI = g_fi[grp][slot * 32];

    // zero h state by COLUMN ownership
    for (int i = tid; i < 32 * 32; i += 256) {
        int r = i >> 5, c = (i & 31) * 2;
        size_t j = (rbase + r) * H_ + cbaseB + c;
        *(__nv_bfloat162*)&g_hh[j] = __nv_bfloat162{__float2bfloat16(0.f), __float2bfloat16(0.f)};
        *(__nv_bfloat162*)&g_hl[j] = __nv_bfloat162{__float2bfloat16(0.f), __float2bfloat16(0.f)};
    }
    __syncthreads();
    if (tid == 0) publish(&g_fh[grp][slot * 32], baseH + 1);

    // resident phase-A weights
    for (int i = tid; i < 32 * 128; i += 256) {
        int r = i >> 7, c = i & 127;
        int d = r * 1024 + ((c ^ (r & 7)) << 3);
        *(uint4*)(smWH + d) = *(const uint4*)&g_w1hTh[(size_t)(cbaseA + r) * H_ + c * 8];
        *(uint4*)(smWL + d) = *(const uint4*)&g_w1hTl[(size_t)(cbaseA + r) * H_ + c * 8];
    }
    __syncthreads();

    const size_t rg0 = rbase + wm * 16 + (lane >> 2);
    const size_t rg1 = rg0 + 8;
    const int len0 = lens[rg0], len1 = lens[rg1];
    const int cgA = cbaseA + wn * 8 + (lane & 3) * 2;
    const float pb1_0 = b1h[cgA], pb1_1 = b1h[cgA + 1];
    float pb2[2][2];
#pragma unroll
    for (int nf = 0; nf < 2; nf++) {
        int cg = cbaseB + wn * 16 + nf * 8 + (lane & 3) * 2;
        pb2[nf][0] = b2h[cg];
        pb2[nf][1] = b2h[cg + 1];
    }
    float h_prev[2][4];
#pragma unroll
    for (int nf = 0; nf < 2; nf++)
#pragma unroll
        for (int q = 0; q < 4; q++) h_prev[nf][q] = 0.f;

    for (int t = 0; t < S_; t++) {
        const unsigned tgtH = baseH + (unsigned)t + 1;
        const unsigned tgtI = baseI + (unsigned)t + 1;
        const int par = t & 1;
        const bf16* ihr = g_ih[par];
        const bf16* ilr = g_il[par];

        // xh prefetch (flag-independent)
        float2 xv[2][2];
#pragma unroll
        for (int nf = 0; nf < 2; nf++) {
            int cg = cbaseB + wn * 16 + nf * 8 + (lane & 3) * 2;
            xv[nf][0] = *(const float2*)&g_xh[(rg0 * S_ + t) * H_ + cg];
            xv[nf][1] = *(const float2*)&g_xh[(rg1 * S_ + t) * H_ + cg];
        }

        // ---- phase A prologue: flags + issue chunks 0..5 (6 stages) ----
#pragma unroll
        for (int p = 0; p < 6; p++) {
            wait_flags(g_fh[grp] + 2 * p * 32, 2, tgtH, lane);
            bf16* hs = sm + RD + p * PA_STAGE;
            ld_sw<32, 16>(hs, g_hh, rbase, H_, p * 128, tid);
            ld_sw<32, 16>(hs + 4096, g_hl, rbase, H_, p * 128, tid);
            CP_COMMIT();
        }

        // ================= phase A =================
        float accA[3][4];
#pragma unroll
        for (int i = 0; i < 3; i++)
#pragma unroll
            for (int q = 0; q < 4; q++) accA[i][q] = 0.f;

#pragma unroll
        for (int kc = 0; kc < 8; kc++) {
            if (kc == 0) { CP_WAIT(5); }
            else if (kc <= 3) { CP_WAIT(4); }
            else if (kc == 4) { CP_WAIT(3); }
            else if (kc == 5) { CP_WAIT(2); }
            else if (kc == 6) { CP_WAIT(1); }
            else { CP_WAIT(0); }
            __syncthreads();
            if (kc == 1 || kc == 2) {   // issue chunks 6,7 into freed stages
                int c = kc + 5;
                wait_flags(g_fh[grp] + 2 * c * 32, 2, tgtH, lane);
                bf16* ns = sm + RD + (c - 6) * PA_STAGE;
                ld_sw<32, 16>(ns, g_hh, rbase, H_, c * 128, tid);
                ld_sw<32, 16>(ns + 4096, g_hl, rbase, H_, c * 128, tid);
                CP_COMMIT();
            }
            bf16* hs = sm + RD + (kc % 6) * PA_STAGE;
#pragma unroll
            for (int ks = 0; ks < 8; ks++) {
                int ko = ks * 16;
                uint32_t ah[4], al[4], bb[4];
                ldsm4_s(ah, hs, 128, wm * 16, ko, lane);
                ldsm4_s(al, hs + 4096, 128, wm * 16, ko, lane);
                ldsm4_bf(bb, smWH, smWL, 1024, wn * 8, kc * 128 + ko, lane);
                hmma(accA[0], ah, bb);
                hmma(accA[1], ah, bb + 2);
                hmma(accA[2], al, bb);
            }
        }
        __syncthreads();   // all warps done with stages before phase B reuses region

        // ---- epilogue A: relu + split -> inter (buffer t&1) ----
#pragma unroll
        for (int half = 0; half < 2; half++) {
            size_t rg = (half == 0) ? rg0 : rg1;
            float v0 = fmaxf(accA[0][half * 2] + accA[1][half * 2] +
                             accA[2][half * 2] + pb1_0, 0.f);
            float v1 = fmaxf(accA[0][half * 2 + 1] + accA[1][half * 2 + 1] +
                             accA[2][half * 2 + 1] + pb1_1, 0.f);
            __nv_bfloat162 hv, lv;
            hv.x = __float2bfloat16(v0);
            hv.y = __float2bfloat16(v1);
            lv.x = __float2bfloat16(v0 - __bfloat162float(hv.x));
            lv.y = __float2bfloat16(v1 - __bfloat162float(hv.y));
            *(__nv_bfloat162*)&g_ih[par][rg * HH_ + cgA] = hv;
            *(__nv_bfloat162*)&g_il[par][rg * HH_ + cgA] = lv;
        }
        __syncthreads();
        if (tid == 0) publish(&g_fi[grp][slot * 32], tgtI);

        // W2 prefetch chunks 0,1 (flag-independent)
        ld_sw<64, 16>(sm + RD + PB_WH, g_w2hTh, (size_t)cbaseB, HH_, 0, tid);
        ld_sw<64, 16>(sm + RD + PB_WL, g_w2hTl, (size_t)cbaseB, HH_, 0, tid);
        CP_COMMIT();
        ld_sw<64, 16>(sm + RD + PB_STAGE + PB_WH, g_w2hTh, (size_t)cbaseB, HH_, 128, tid);
        ld_sw<64, 16>(sm + RD + PB_STAGE + PB_WL, g_w2hTl, (size_t)cbaseB, HH_, 128, tid);
        CP_COMMIT();

        // wait inter cols 0..255 (CTAs 0..7), issue inter chunks 0,1
        wait_flags(g_fi[grp], 8, tgtI, lane);
        ld_sw<32, 16>(sm + RD + PB_AH, ihr, rbase, HH_, 0, tid);
        ld_sw<32, 16>(sm + RD + PB_AL, ilr, rbase, HH_, 0, tid);
        CP_COMMIT();
        ld_sw<32, 16>(sm + RD + PB_STAGE + PB_AH, ihr, rbase, HH_, 128, tid);
        ld_sw<32, 16>(sm + RD + PB_STAGE + PB_AL, ilr, rbase, HH_, 128, tid);
        CP_COMMIT();

        // ================= phase B =================
        float accB[2][3][4];
#pragma unroll
        for (int nf = 0; nf < 2; nf++)
#pragma unroll
            for (int i = 0; i < 3; i++)
#pragma unroll
                for (int q = 0; q < 4; q++) accB[nf][i][q] = 0.f;

#pragma unroll
        for (int kc = 0; kc < 4; kc++) {
            if (kc < 3) { CP_WAIT(1); } else { CP_WAIT(0); }
            __syncthreads();
            bf16* cb = sm + RD + (kc & 1) * PB_STAGE;
#pragma unroll
            for (int ks = 0; ks < 8; ks++) {
                int ko = ks * 16;
                uint32_t ah[4], al[4], bh4[4], bl4[4];
                ldsm4_s(ah, cb + PB_AH, 128, wm * 16, ko, lane);
                ldsm4_s(al, cb + PB_AL, 128, wm * 16, ko, lane);
                ldsm4_n16(bh4, cb + PB_WH, 128, wn * 16, ko, lane);
                ldsm4_n16(bl4, cb + PB_WL, 128, wn * 16, ko, lane);
#pragma unroll
                for (int nf = 0; nf < 2; nf++) {
                    hmma(accB[nf][0], ah, bh4 + 2 * nf);
                    hmma(accB[nf][1], ah, bl4 + 2 * nf);
                    hmma(accB[nf][2], al, bh4 + 2 * nf);
                }
            }
            __syncthreads();
            if (kc < 2) {
                wait_flags(g_fi[grp] + (8 + 4 * kc) * 32, 4, tgtI, lane);
                bf16* ns = sm + RD + (kc & 1) * PB_STAGE;
                int k0 = (kc + 2) * 128;
                ld_sw<32, 16>(ns + PB_AH, ihr, rbase, HH_, k0, tid);
                ld_sw<32, 16>(ns + PB_AL, ilr, rbase, HH_, k0, tid);
                ld_sw<64, 16>(ns + PB_WH, g_w2hTh, (size_t)cbaseB, HH_, k0, tid);
                ld_sw<64, 16>(ns + PB_WL, g_w2hTl, (size_t)cbaseB, HH_, k0, tid);
                CP_COMMIT();
            }
        }

        // ---- epilogue B ----
#pragma unroll
        for (int nf = 0; nf < 2; nf++) {
            int cg = cbaseB + wn * 16 + nf * 8 + (lane & 3) * 2;
#pragma unroll
            for (int half = 0; half < 2; half++) {
                size_t rg = (half == 0) ? rg0 : rg1;
                bool on = t < ((half == 0) ? len0 : len1);
                float v0, v1;
                if (on) {
                    float s0 = accB[nf][0][half * 2] + accB[nf][1][half * 2] +
                               accB[nf][2][half * 2];
                    float s1 = accB[nf][0][half * 2 + 1] + accB[nf][1][half * 2 + 1] +
                               accB[nf][2][half * 2 + 1];
                    v0 = fast_tanh(xv[nf][half].x + s0 + pb2[nf][0]);
                    v1 = fast_tanh(xv[nf][half].y + s1 + pb2[nf][1]);
                    h_prev[nf][half * 2] = v0;
                    h_prev[nf][half * 2 + 1] = v1;
                    __nv_bfloat162 hv, lv;
                    hv.x = __float2bfloat16(v0);
                    hv.y = __float2bfloat16(v1);
                    lv.x = __float2bfloat16(v0 - __bfloat162float(hv.x));
                    lv.y = __float2bfloat16(v1 - __bfloat162float(hv.y));
                    *(__nv_bfloat162*)&g_hh[rg * H_ + cg] = hv;
                    *(__nv_bfloat162*)&g_hl[rg * H_ + cg] = lv;
                } else {
                    v0 = h_prev[nf][half * 2];
                    v1 = h_prev[nf][half * 2 + 1];
                }
                *(float2*)&out[(rg * S_ + t) * H_ + cg] = make_float2(v0, v1);
            }
        }
        __syncthreads();
        if (tid == 0) publish(&g_fh[grp][slot * 32], baseH + (unsigned)t + 2);
    }
}

// ---------------- launcher --------------------------------------------------
extern "C" void kernel_launch(void* const* d_in, const int* in_sizes, int n_in,
                              void* d_out, int out_size) {
    const float* seq = (const float*)d_in[0];
    const int* lens  = (const int*)d_in[1];
    const float* w1x = (const float*)d_in[2];
    const float* b1x = (const float*)d_in[3];
    const float* w2x = (const float*)d_in[4];
    const float* b2x = (const float*)d_in[5];
    const float* w1h = (const float*)d_in[6];
    const float* b1h = (const float*)d_in[7];
    const float* w2h = (const float*)d_in[8];
    const float* b2h = (const float*)d_in[9];
    float* out = (float*)d_out;

    bf16 *seqh, *seql, *tmph, *tmpl;
    bf16 *w1xh, *w1xl, *w2xh, *w2xl, *w1hh, *w1hl, *w2hh, *w2hl;
    float* xh;
    cudaGetSymbolAddress((void**)&seqh, g_seqh);
    cudaGetSymbolAddress((void**)&seql, g_seql);
    cudaGetSymbolAddress((void**)&tmph, g_tmph);
    cudaGetSymbolAddress((void**)&tmpl, g_tmpl);
    cudaGetSymbolAddress((void**)&xh, g_xh);
    cudaGetSymbolAddress((void**)&w1xh, g_w1xTh);
    cudaGetSymbolAddress((void**)&w1xl, g_w1xTl);
    cudaGetSymbolAddress((void**)&w2xh, g_w2xTh);
    cudaGetSymbolAddress((void**)&w2xl, g_w2xTl);
    cudaGetSymbolAddress((void**)&w1hh, g_w1hTh);
    cudaGetSymbolAddress((void**)&w1hl, g_w1hTl);
    cudaGetSymbolAddress((void**)&w2hh, g_w2hTh);
    cudaGetSymbolAddress((void**)&w2hl, g_w2hTl);

    cudaFuncSetAttribute(ff_mma, cudaFuncAttributeMaxDynamicSharedMemorySize, P1_SMEM);
    cudaFuncSetAttribute(recurrence, cudaFuncAttributeMaxDynamicSharedMemorySize, R_SMEM);

    size_t nseq = (size_t)MTOK * E_;
    split_kernel<<<(unsigned)((nseq + 255) / 256), 256>>>(seq, seqh, seql, nseq);
    transpose_split<<<(E_ * HH_ + 255) / 256, 256>>>(w1x, w1xh, w1xl, E_, HH_);
    transpose_split<<<(HH_ * H_ + 255) / 256, 256>>>(w2x, w2xh, w2xl, HH_, H_);
    transpose_split<<<(H_ * HH_ + 255) / 256, 256>>>(w1h, w1hh, w1hl, H_, HH_);
    transpose_split<<<(HH_ * H_ + 255) / 256, 256>>>(w2h, w2hh, w2hl, HH_, H_);

    ff_mma<<<dim3(HH_ / 128, MTOK / 128), 256, P1_SMEM>>>(
        seqh, seql, w1xh, w1xl, b1x, nullptr, tmph, tmpl, E_, HH_, 1);
    ff_mma<<<dim3(H_ / 128, MTOK / 128), 256, P1_SMEM>>>(
        tmph, tmpl, w2xh, w2xl, b2x, xh, nullptr, nullptr, HH_, H_, 0);

    recurrence<<<128, 256, R_SMEM>>>(b1h, b2h, lens, out);
}

// round 12
// speedup vs baseline: 1.0286x; 1.0286x over previous
#include <cuda_runtime.h>
#include <cuda_bf16.h>
#include <cstdint>

#define B_ 256
#define S_ 512
#define E_ 512
#define H_ 1024
#define HH_ 512
#define MTOK (B_ * S_)

typedef __nv_bfloat16 bf16;

// ---------------- device-global scratch ------------------------------------
__device__ bf16 g_seqh[(size_t)MTOK * E_];
__device__ bf16 g_seql[(size_t)MTOK * E_];
__device__ bf16 g_tmph[(size_t)MTOK * HH_];
__device__ bf16 g_tmpl[(size_t)MTOK * HH_];
__device__ float g_xh[(size_t)MTOK * H_];
__device__ bf16 g_w1xTh[HH_ * E_], g_w1xTl[HH_ * E_];   // [N,K]
__device__ bf16 g_w2xTh[H_ * HH_], g_w2xTl[H_ * HH_];
__device__ bf16 g_w1hTh[HH_ * H_], g_w1hTl[HH_ * H_];
__device__ bf16 g_w2hTh[H_ * HH_], g_w2hTl[H_ * HH_];
__device__ bf16 g_hh[B_ * H_], g_hl[B_ * H_];
__device__ bf16 g_ih[2][B_ * HH_], g_il[2][B_ * HH_];   // inter double-buffered
// monotonic per-CTA flags (128B stride per flag)
__device__ volatile unsigned g_fh[8][16 * 32];
__device__ volatile unsigned g_fi[8][16 * 32];

// ---------------- helpers ----------------------------------------------------
__device__ __forceinline__ uint32_t smem_u32(const void* p) {
    uint32_t r;
    asm("{ .reg .u64 t; cvta.to.shared.u64 t, %1; cvt.u32.u64 %0, t; }" : "=r"(r) : "l"(p));
    return r;
}
__device__ __forceinline__ float fast_tanh(float x) {
    float y; asm("tanh.approx.f32 %0, %1;" : "=f"(y) : "f"(x)); return y;
}
__device__ __forceinline__ void hmma(float c[4], const uint32_t a[4], const uint32_t b[2]) {
    asm volatile("mma.sync.aligned.m16n8k16.row.col.f32.bf16.bf16.f32 "
        "{%0,%1,%2,%3}, {%4,%5,%6,%7}, {%8,%9}, {%0,%1,%2,%3};"
        : "+f"(c[0]), "+f"(c[1]), "+f"(c[2]), "+f"(c[3])
        : "r"(a[0]), "r"(a[1]), "r"(a[2]), "r"(a[3]), "r"(b[0]), "r"(b[1]));
}
// swizzled ldmatrix x4: A frag m16k16
__device__ __forceinline__ void ldsm4_s(uint32_t a[4], const bf16* tb, int rowlen,
                                        int rowbase, int ko, int lane) {
    int row = rowbase + (lane & 15);
    int seg = (ko >> 3) + (lane >> 4);
    uint32_t addr = smem_u32(tb + row * rowlen + ((seg ^ (row & 7)) << 3));
    asm volatile("ldmatrix.sync.aligned.m8n8.x4.shared.b16 {%0,%1,%2,%3}, [%4];"
        : "=r"(a[0]), "=r"(a[1]), "=r"(a[2]), "=r"(a[3]) : "r"(addr));
}
// fused x4: B frags for TWO adjacent n8 blocks (n16): b[0..1]=nf0, b[2..3]=nf1
__device__ __forceinline__ void ldsm4_n16(uint32_t b[4], const bf16* tb, int rowlen,
                                          int rowbase, int ko, int lane) {
    int row = rowbase + ((lane >> 4) << 3) + (lane & 7);
    int seg = (ko >> 3) + ((lane >> 3) & 1);
    uint32_t addr = smem_u32(tb + row * rowlen + ((seg ^ (row & 7)) << 3));
    asm volatile("ldmatrix.sync.aligned.m8n8.x4.shared.b16 {%0,%1,%2,%3}, [%4];"
        : "=r"(b[0]), "=r"(b[1]), "=r"(b[2]), "=r"(b[3]) : "r"(addr));
}
__device__ __forceinline__ void ldsm2_s(uint32_t b[2], const bf16* tb, int rowlen,
                                        int rowbase, int ko, int lane) {
    int row = rowbase + (lane & 7);
    int seg = (ko >> 3) + ((lane >> 3) & 1);
    uint32_t addr = smem_u32(tb + row * rowlen + ((seg ^ (row & 7)) << 3));
    asm volatile("ldmatrix.sync.aligned.m8n8.x2.shared.b16 {%0,%1}, [%2];"
        : "=r"(b[0]), "=r"(b[1]) : "r"(addr));
}
__device__ __forceinline__ void cp16(bf16* s, const bf16* g) {
    uint32_t sa = smem_u32(s);
    asm volatile("cp.async.cg.shared.global [%0], [%1], 16;" :: "r"(sa), "l"(g));
}
#define CP_COMMIT() asm volatile("cp.async.commit_group;" ::: "memory")
#define CP_WAIT(n) asm volatile("cp.async.wait_group %0;" :: "n"(n) : "memory")

// async-load [ROWS x SEGS*8] bf16 tile, swizzled
template <int ROWS, int SEGS>
__device__ __forceinline__ void ld_sw(bf16* dst, const bf16* __restrict__ src,
                                      size_t row0, int ld, int k0, int tid) {
#pragma unroll
    for (int i = tid; i < ROWS * SEGS; i += 256) {
        int r = i / SEGS, c = i % SEGS;
        cp16(dst + r * SEGS * 8 + ((c ^ (r & 7)) << 3),
             src + (row0 + (size_t)r) * (size_t)ld + k0 + c * 8);
    }
}

// warp-parallel acquire poll on cnt flags (cnt power of 2); all threads call
__device__ __forceinline__ void wait_flags(volatile unsigned* fl, int cnt,
                                           unsigned tgt, int lane) {
    const unsigned* p = (const unsigned*)(fl + (lane & (cnt - 1)) * 32);
    unsigned v;
    do {
        asm volatile("ld.acquire.gpu.u32 %0, [%1];" : "=r"(v) : "l"(p) : "memory");
    } while (__any_sync(0xffffffffu, (int)(v - tgt) < 0));
}
__device__ __forceinline__ void publish(volatile unsigned* fl, unsigned val) {
    __threadfence();
    asm volatile("st.release.gpu.u32 [%0], %1;" :: "l"((unsigned*)fl), "r"(val) : "memory");
}

// ---------------- prep kernels ----------------------------------------------
__global__ void split_kernel(const float* __restrict__ x, bf16* __restrict__ h,
                             bf16* __restrict__ l, size_t n) {
    size_t i = (size_t)blockIdx.x * 256 + threadIdx.x;
    if (i < n) {
        float v = x[i];
        bf16 a = __float2bfloat16(v);
        h[i] = a;
        l[i] = __float2bfloat16(v - __bfloat162float(a));
    }
}
__global__ void transpose_split(const float* __restrict__ W, bf16* __restrict__ Th,
                                bf16* __restrict__ Tl, int K, int N) {
    int idx = blockIdx.x * 256 + threadIdx.x;
    if (idx < N * K) {
        int n = idx / K, k = idx % K;
        float v = W[k * N + n];
        bf16 a = __float2bfloat16(v);
        Th[idx] = a;
        Tl[idx] = __float2bfloat16(v - __bfloat162float(a));
    }
}

// ---------------- phase-1 GEMM: out = act(A @ W^T + bias) -------------------
#define P1_AH 0
#define P1_AL 8192
#define P1_BH 16384
#define P1_BL 24576
#define P1_BUF 32768
#define P1_SMEM (2 * P1_BUF * 2)

__global__ __launch_bounds__(256) void ff_mma(
    const bf16* __restrict__ Ah, const bf16* __restrict__ Al,
    const bf16* __restrict__ Bh, const bf16* __restrict__ Bl,
    const float* __restrict__ bias, float* __restrict__ outF,
    bf16* __restrict__ outH, bf16* __restrict__ outL,
    int K, int N, int relu_split)
{
    extern __shared__ bf16 sm[];
    bf16* buf[2] = {sm, sm + P1_BUF};
    const int tid = threadIdx.x, lane = tid & 31, wid = tid >> 5;
    const int wm = wid & 3, wn = wid >> 2;
    const size_t rowBase = (size_t)blockIdx.y * 128;
    const int colBase = blockIdx.x * 128;
    const int nch = K / 64;

    float acc[2][8][4];
#pragma unroll
    for (int i = 0; i < 2; i++)
#pragma unroll
        for (int j = 0; j < 8; j++)
#pragma unroll
            for (int q = 0; q < 4; q++) acc[i][j][q] = 0.f;

    ld_sw<128, 8>(buf[0] + P1_AH, Ah, rowBase, K, 0, tid);
    ld_sw<128, 8>(buf[0] + P1_AL, Al, rowBase, K, 0, tid);
    ld_sw<128, 8>(buf[0] + P1_BH, Bh, (size_t)colBase, K, 0, tid);
    ld_sw<128, 8>(buf[0] + P1_BL, Bl, (size_t)colBase, K, 0, tid);
    CP_COMMIT();

    for (int kc = 0; kc < nch; kc++) {
        if (kc < nch - 1) {
            bf16* nb = buf[(kc + 1) & 1];
            int k0 = (kc + 1) * 64;
            ld_sw<128, 8>(nb + P1_AH, Ah, rowBase, K, k0, tid);
            ld_sw<128, 8>(nb + P1_AL, Al, rowBase, K, k0, tid);
            ld_sw<128, 8>(nb + P1_BH, Bh, (size_t)colBase, K, k0, tid);
            ld_sw<128, 8>(nb + P1_BL, Bl, (size_t)colBase, K, k0, tid);
            CP_COMMIT();
            CP_WAIT(1);
        } else {
            CP_WAIT(0);
        }
        __syncthreads();
        bf16* cb = buf[kc & 1];
#pragma unroll
        for (int ks = 0; ks < 4; ks++) {
            int ko = ks * 16;
            uint32_t ah[2][4], al[2][4];
#pragma unroll
            for (int mf = 0; mf < 2; mf++) {
                ldsm4_s(ah[mf], cb + P1_AH, 64, wm * 32 + mf * 16, ko, lane);
                ldsm4_s(al[mf], cb + P1_AL, 64, wm * 32 + mf * 16, ko, lane);
            }
#pragma unroll
            for (int nf = 0; nf < 8; nf++) {
                uint32_t bh[2], bl[2];
                ldsm2_s(bh, cb + P1_BH, 64, wn * 64 + nf * 8, ko, lane);
                ldsm2_s(bl, cb + P1_BL, 64, wn * 64 + nf * 8, ko, lane);
#pragma unroll
                for (int mf = 0; mf < 2; mf++) {
                    hmma(acc[mf][nf], ah[mf], bh);
                    hmma(acc[mf][nf], ah[mf], bl);
                    hmma(acc[mf][nf], al[mf], bh);
                }
            }
        }
        __syncthreads();
    }

#pragma unroll
    for (int mf = 0; mf < 2; mf++) {
#pragma unroll
        for (int nf = 0; nf < 8; nf++) {
            int cg = colBase + wn * 64 + nf * 8 + (lane & 3) * 2;
            float b0 = bias[cg], b1 = bias[cg + 1];
#pragma unroll
            for (int half = 0; half < 2; half++) {
                size_t rg = rowBase + wm * 32 + mf * 16 + (lane >> 2) + half * 8;
                float v0 = acc[mf][nf][half * 2] + b0;
                float v1 = acc[mf][nf][half * 2 + 1] + b1;
                if (relu_split) {
                    v0 = fmaxf(v0, 0.f);
                    v1 = fmaxf(v1, 0.f);
                    __nv_bfloat162 hv, lv;
                    hv.x = __float2bfloat16(v0);
                    hv.y = __float2bfloat16(v1);
                    lv.x = __float2bfloat16(v0 - __bfloat162float(hv.x));
                    lv.y = __float2bfloat16(v1 - __bfloat162float(hv.y));
                    *(__nv_bfloat162*)&outH[rg * N + cg] = hv;
                    *(__nv_bfloat162*)&outL[rg * N + cg] = lv;
                } else {
                    *(float2*)&outF[rg * N + cg] = make_float2(v0, v1);
                }
            }
        }
    }
}

// ---------------- persistent recurrence: 8 groups x 16 CTAs -----------------
// R10 structure; changes: early h-flag publish in epilogue B + streaming out
// stores; phase B uses n16-fused ldmatrix.
#define RW_H 0
#define RW_L 32768
#define RD 65536
#define PB_AH 0
#define PB_AL 4096
#define PB_WH 8192
#define PB_WL 16384
#define PB_STAGE 24576
#define PA_STAGE 8192
#define R_SMEM ((65536 + 2 * 24576) * 2)

__global__ __launch_bounds__(256) void recurrence(
    const float* __restrict__ b1h, const float* __restrict__ b2h,
    const int* __restrict__ lens, float* __restrict__ out)
{
    extern __shared__ bf16 sm[];
    bf16* smWH = sm + RW_H;
    bf16* smWL = sm + RW_L;
    const int tid = threadIdx.x, lane = tid & 31, wid = tid >> 5;
    const int wm = wid & 1, wn = wid >> 1;  // 2m x 4n warps
    const int cta = blockIdx.x;
    const int grp = cta >> 4;
    const int slot = cta & 15;
    const size_t rbase = (size_t)grp * 32;
    const int cbaseA = slot * 32;
    const int cbaseB = slot * 64;

    const unsigned baseH = g_fh[grp][slot * 32];
    const unsigned baseI = g_fi[grp][slot * 32];

    // zero h state by COLUMN ownership
    for (int i = tid; i < 32 * 32; i += 256) {
        int r = i >> 5, c = (i & 31) * 2;
        size_t j = (rbase + r) * H_ + cbaseB + c;
        *(__nv_bfloat162*)&g_hh[j] = __nv_bfloat162{__float2bfloat16(0.f), __float2bfloat16(0.f)};
        *(__nv_bfloat162*)&g_hl[j] = __nv_bfloat162{__float2bfloat16(0.f), __float2bfloat16(0.f)};
    }
    __syncthreads();
    if (tid == 0) publish(&g_fh[grp][slot * 32], baseH + 1);

    // resident phase-A weights
    for (int i = tid; i < 32 * 128; i += 256) {
        int r = i >> 7, c = i & 127;
        int d = r * 1024 + ((c ^ (r & 7)) << 3);
        *(uint4*)(smWH + d) = *(const uint4*)&g_w1hTh[(size_t)(cbaseA + r) * H_ + c * 8];
        *(uint4*)(smWL + d) = *(const uint4*)&g_w1hTl[(size_t)(cbaseA + r) * H_ + c * 8];
    }
    __syncthreads();

    const size_t rg0 = rbase + wm * 16 + (lane >> 2);
    const size_t rg1 = rg0 + 8;
    const int len0 = lens[rg0], len1 = lens[rg1];
    const int cgA = cbaseA + wn * 8 + (lane & 3) * 2;
    const float pb1_0 = b1h[cgA], pb1_1 = b1h[cgA + 1];
    float pb2[2][2];
#pragma unroll
    for (int nf = 0; nf < 2; nf++) {
        int cg = cbaseB + wn * 16 + nf * 8 + (lane & 3) * 2;
        pb2[nf][0] = b2h[cg];
        pb2[nf][1] = b2h[cg + 1];
    }
    float h_prev[2][4];
#pragma unroll
    for (int nf = 0; nf < 2; nf++)
#pragma unroll
        for (int q = 0; q < 4; q++) h_prev[nf][q] = 0.f;

    for (int t = 0; t < S_; t++) {
        const unsigned tgtH = baseH + (unsigned)t + 1;
        const unsigned tgtI = baseI + (unsigned)t + 1;
        const int par = t & 1;
        const bf16* ihr = g_ih[par];
        const bf16* ilr = g_il[par];

        // xh prefetch (flag-independent)
        float2 xv[2][2];
#pragma unroll
        for (int nf = 0; nf < 2; nf++) {
            int cg = cbaseB + wn * 16 + nf * 8 + (lane & 3) * 2;
            xv[nf][0] = *(const float2*)&g_xh[(rg0 * S_ + t) * H_ + cg];
            xv[nf][1] = *(const float2*)&g_xh[(rg1 * S_ + t) * H_ + cg];
        }

        // wait h cols 0..511 (CTAs 0..7), then issue phase-A chunks 0..3
        wait_flags(g_fh[grp], 8, tgtH, lane);
#pragma unroll
        for (int p = 0; p < 4; p++) {
            bf16* hs = sm + RD + p * PA_STAGE;
            ld_sw<32, 16>(hs, g_hh, rbase, H_, p * 128, tid);
            ld_sw<32, 16>(hs + 4096, g_hl, rbase, H_, p * 128, tid);
            CP_COMMIT();
        }

        // ================= phase A =================
        float accA[3][4];
#pragma unroll
        for (int i = 0; i < 3; i++)
#pragma unroll
            for (int q = 0; q < 4; q++) accA[i][q] = 0.f;

#pragma unroll
        for (int kc = 0; kc < 8; kc++) {
            if (kc <= 4) { CP_WAIT(3); }
            else if (kc == 5) { CP_WAIT(2); }
            else if (kc == 6) { CP_WAIT(1); }
            else { CP_WAIT(0); }
            __syncthreads();
            bf16* hs = sm + RD + (kc & 3) * PA_STAGE;
#pragma unroll
            for (int ks = 0; ks < 8; ks++) {
                int ko = ks * 16;
                uint32_t ah[4], al[4], bh[2], bl[2];
                ldsm4_s(ah, hs, 128, wm * 16, ko, lane);
                ldsm4_s(al, hs + 4096, 128, wm * 16, ko, lane);
                ldsm2_s(bh, smWH, 1024, wn * 8, kc * 128 + ko, lane);
                ldsm2_s(bl, smWL, 1024, wn * 8, kc * 128 + ko, lane);
                hmma(accA[0], ah, bh);
                hmma(accA[1], ah, bl);
                hmma(accA[2], al, bh);
            }
            __syncthreads();
            if (kc < 4) {
                wait_flags(g_fh[grp] + (8 + 2 * kc) * 32, 2, tgtH, lane);
                bf16* ns = sm + RD + (kc & 3) * PA_STAGE;
                ld_sw<32, 16>(ns, g_hh, rbase, H_, (kc + 4) * 128, tid);
                ld_sw<32, 16>(ns + 4096, g_hl, rbase, H_, (kc + 4) * 128, tid);
                CP_COMMIT();
            }
        }

        // ---- epilogue A: relu + split -> inter (buffer t&1) ----
#pragma unroll
        for (int half = 0; half < 2; half++) {
            size_t rg = (half == 0) ? rg0 : rg1;
            float v0 = fmaxf(accA[0][half * 2] + accA[1][half * 2] +
                             accA[2][half * 2] + pb1_0, 0.f);
            float v1 = fmaxf(accA[0][half * 2 + 1] + accA[1][half * 2 + 1] +
                             accA[2][half * 2 + 1] + pb1_1, 0.f);
            __nv_bfloat162 hv, lv;
            hv.x = __float2bfloat16(v0);
            hv.y = __float2bfloat16(v1);
            lv.x = __float2bfloat16(v0 - __bfloat162float(hv.x));
            lv.y = __float2bfloat16(v1 - __bfloat162float(hv.y));
            *(__nv_bfloat162*)&g_ih[par][rg * HH_ + cgA] = hv;
            *(__nv_bfloat162*)&g_il[par][rg * HH_ + cgA] = lv;
        }
        __syncthreads();
        if (tid == 0) publish(&g_fi[grp][slot * 32], tgtI);

        // W2 prefetch chunks 0,1 (flag-independent)
        ld_sw<64, 16>(sm + RD + PB_WH, g_w2hTh, (size_t)cbaseB, HH_, 0, tid);
        ld_sw<64, 16>(sm + RD + PB_WL, g_w2hTl, (size_t)cbaseB, HH_, 0, tid);
        CP_COMMIT();
        ld_sw<64, 16>(sm + RD + PB_STAGE + PB_WH, g_w2hTh, (size_t)cbaseB, HH_, 128, tid);
        ld_sw<64, 16>(sm + RD + PB_STAGE + PB_WL, g_w2hTl, (size_t)cbaseB, HH_, 128, tid);
        CP_COMMIT();

        // wait inter cols 0..255 (CTAs 0..7), issue inter chunks 0,1
        wait_flags(g_fi[grp], 8, tgtI, lane);
        ld_sw<32, 16>(sm + RD + PB_AH, ihr, rbase, HH_, 0, tid);
        ld_sw<32, 16>(sm + RD + PB_AL, ilr, rbase, HH_, 0, tid);
        CP_COMMIT();
        ld_sw<32, 16>(sm + RD + PB_STAGE + PB_AH, ihr, rbase, HH_, 128, tid);
        ld_sw<32, 16>(sm + RD + PB_STAGE + PB_AL, ilr, rbase, HH_, 128, tid);
        CP_COMMIT();

        // ================= phase B =================
        float accB[2][3][4];
#pragma unroll
        for (int nf = 0; nf < 2; nf++)
#pragma unroll
            for (int i = 0; i < 3; i++)
#pragma unroll
                for (int q = 0; q < 4; q++) accB[nf][i][q] = 0.f;

#pragma unroll
        for (int kc = 0; kc < 4; kc++) {
            if (kc < 3) { CP_WAIT(1); } else { CP_WAIT(0); }
            __syncthreads();
            bf16* cb = sm + RD + (kc & 1) * PB_STAGE;
#pragma unroll
            for (int ks = 0; ks < 8; ks++) {
                int ko = ks * 16;
                uint32_t ah[4], al[4], bh4[4], bl4[4];
                ldsm4_s(ah, cb + PB_AH, 128, wm * 16, ko, lane);
                ldsm4_s(al, cb + PB_AL, 128, wm * 16, ko, lane);
                ldsm4_n16(bh4, cb + PB_WH, 128, wn * 16, ko, lane);
                ldsm4_n16(bl4, cb + PB_WL, 128, wn * 16, ko, lane);
#pragma unroll
                for (int nf = 0; nf < 2; nf++) {
                    hmma(accB[nf][0], ah, bh4 + 2 * nf);
                    hmma(accB[nf][1], ah, bl4 + 2 * nf);
                    hmma(accB[nf][2], al, bh4 + 2 * nf);
                }
            }
            __syncthreads();
            if (kc < 2) {
                wait_flags(g_fi[grp] + (8 + 4 * kc) * 32, 4, tgtI, lane);
                bf16* ns = sm + RD + (kc & 1) * PB_STAGE;
                int k0 = (kc + 2) * 128;
                ld_sw<32, 16>(ns + PB_AH, ihr, rbase, HH_, k0, tid);
                ld_sw<32, 16>(ns + PB_AL, ilr, rbase, HH_, k0, tid);
                ld_sw<64, 16>(ns + PB_WH, g_w2hTh, (size_t)cbaseB, HH_, k0, tid);
                ld_sw<64, 16>(ns + PB_WL, g_w2hTl, (size_t)cbaseB, HH_, k0, tid);
                CP_COMMIT();
            }
        }

        // ---- epilogue B: compute + h-state stores FIRST, publish, then out --
        float res[2][2][2];
#pragma unroll
        for (int nf = 0; nf < 2; nf++) {
            int cg = cbaseB + wn * 16 + nf * 8 + (lane & 3) * 2;
#pragma unroll
            for (int half = 0; half < 2; half++) {
                bool on = t < ((half == 0) ? len0 : len1);
                size_t rg = (half == 0) ? rg0 : rg1;
                float v0, v1;
                if (on) {
                    float s0 = accB[nf][0][half * 2] + accB[nf][1][half * 2] +
                               accB[nf][2][half * 2];
                    float s1 = accB[nf][0][half * 2 + 1] + accB[nf][1][half * 2 + 1] +
                               accB[nf][2][half * 2 + 1];
                    v0 = fast_tanh(xv[nf][half].x + s0 + pb2[nf][0]);
                    v1 = fast_tanh(xv[nf][half].y + s1 + pb2[nf][1]);
                    h_prev[nf][half * 2] = v0;
                    h_prev[nf][half * 2 + 1] = v1;
                    __nv_bfloat162 hv, lv;
                    hv.x = __float2bfloat16(v0);
                    hv.y = __float2bfloat16(v1);
                    lv.x = __float2bfloat16(v0 - __bfloat162float(hv.x));
                    lv.y = __float2bfloat16(v1 - __bfloat162float(hv.y));
                    *(__nv_bfloat162*)&g_hh[rg * H_ + cg] = hv;
                    *(__nv_bfloat162*)&g_hl[rg * H_ + cg] = lv;
                } else {
                    v0 = h_prev[nf][half * 2];
                    v1 = h_prev[nf][half * 2 + 1];
                }
                res[nf][half][0] = v0;
                res[nf][half][1] = v1;
            }
        }
        __syncthreads();
        if (tid == 0) publish(&g_fh[grp][slot * 32], baseH + (unsigned)t + 2);
        // out writes off the critical path, streaming (bypass L2 persistence)
#pragma unroll
        for (int nf = 0; nf < 2; nf++) {
            int cg = cbaseB + wn * 16 + nf * 8 + (lane & 3) * 2;
#pragma unroll
            for (int half = 0; half < 2; half++) {
                size_t rg = (half == 0) ? rg0 : rg1;
                __stcs((float2*)&out[(rg * S_ + t) * H_ + cg],
                       make_float2(res[nf][half][0], res[nf][half][1]));
            }
        }
    }
}

// ---------------- launcher --------------------------------------------------
extern "C" void kernel_launch(void* const* d_in, const int* in_sizes, int n_in,
                              void* d_out, int out_size) {
    const float* seq = (const float*)d_in[0];
    const int* lens  = (const int*)d_in[1];
    const float* w1x = (const float*)d_in[2];
    const float* b1x = (const float*)d_in[3];
    const float* w2x = (const float*)d_in[4];
    const float* b2x = (const float*)d_in[5];
    const float* w1h = (const float*)d_in[6];
    const float* b1h = (const float*)d_in[7];
    const float* w2h = (const float*)d_in[8];
    const float* b2h = (const float*)d_in[9];
    float* out = (float*)d_out;

    bf16 *seqh, *seql, *tmph, *tmpl;
    bf16 *w1xh, *w1xl, *w2xh, *w2xl, *w1hh, *w1hl, *w2hh, *w2hl;
    float* xh;
    cudaGetSymbolAddress((void**)&seqh, g_seqh);
    cudaGetSymbolAddress((void**)&seql, g_seql);
    cudaGetSymbolAddress((void**)&tmph, g_tmph);
    cudaGetSymbolAddress((void**)&tmpl, g_tmpl);
    cudaGetSymbolAddress((void**)&xh, g_xh);
    cudaGetSymbolAddress((void**)&w1xh, g_w1xTh);
    cudaGetSymbolAddress((void**)&w1xl, g_w1xTl);
    cudaGetSymbolAddress((void**)&w2xh, g_w2xTh);
    cudaGetSymbolAddress((void**)&w2xl, g_w2xTl);
    cudaGetSymbolAddress((void**)&w1hh, g_w1hTh);
    cudaGetSymbolAddress((void**)&w1hl, g_w1hTl);
    cudaGetSymbolAddress((void**)&w2hh, g_w2hTh);
    cudaGetSymbolAddress((void**)&w2hl, g_w2hTl);

    cudaFuncSetAttribute(ff_mma, cudaFuncAttributeMaxDynamicSharedMemorySize, P1_SMEM);
    cudaFuncSetAttribute(recurrence, cudaFuncAttributeMaxDynamicSharedMemorySize, R_SMEM);

    size_t nseq = (size_t)MTOK * E_;
    split_kernel<<<(unsigned)((nseq + 255) / 256), 256>>>(seq, seqh, seql, nseq);
    transpose_split<<<(E_ * HH_ + 255) / 256, 256>>>(w1x, w1xh, w1xl, E_, HH_);
    transpose_split<<<(HH_ * H_ + 255) / 256, 256>>>(w2x, w2xh, w2xl, HH_, H_);
    transpose_split<<<(H_ * HH_ + 255) / 256, 256>>>(w1h, w1hh, w1hl, H_, HH_);
    transpose_split<<<(HH_ * H_ + 255) / 256, 256>>>(w2h, w2hh, w2hl, HH_, H_);

    ff_mma<<<dim3(HH_ / 128, MTOK / 128), 256, P1_SMEM>>>(
        seqh, seql, w1xh, w1xl, b1x, nullptr, tmph, tmpl, E_, HH_, 1);
    ff_mma<<<dim3(H_ / 128, MTOK / 128), 256, P1_SMEM>>>(
        tmph, tmpl, w2xh, w2xl, b2x, xh, nullptr, nullptr, HH_, H_, 0);

    recurrence<<<128, 256, R_SMEM>>>(b1h, b2h, lens, out);
}

// round 13
// speedup vs baseline: 1.0691x; 1.0394x over previous
#include <cuda_runtime.h>
#include <cuda_bf16.h>
#include <cstdint>

#define B_ 256
#define S_ 512
#define E_ 512
#define H_ 1024
#define HH_ 512
#define MTOK (B_ * S_)

typedef __nv_bfloat16 bf16;

// ---------------- device-global scratch ------------------------------------
__device__ bf16 g_seqh[(size_t)MTOK * E_];
__device__ bf16 g_seql[(size_t)MTOK * E_];
__device__ bf16 g_tmph[(size_t)MTOK * HH_];
__device__ bf16 g_tmpl[(size_t)MTOK * HH_];
__device__ float g_xh[(size_t)MTOK * H_];
__device__ bf16 g_w1xTh[HH_ * E_], g_w1xTl[HH_ * E_];   // [N,K]
__device__ bf16 g_w2xTh[H_ * HH_], g_w2xTl[H_ * HH_];
__device__ bf16 g_w1hTh[HH_ * H_], g_w1hTl[HH_ * H_];
__device__ bf16 g_w2hTh[H_ * HH_], g_w2hTl[H_ * HH_];
__device__ bf16 g_hh[B_ * H_], g_hl[B_ * H_];
__device__ bf16 g_ih[2][B_ * HH_], g_il[2][B_ * HH_];   // inter double-buffered
// monotonic per-CTA flags (128B stride per flag)
__device__ volatile unsigned g_fh[8][16 * 32];
__device__ volatile unsigned g_fi[8][16 * 32];

// ---------------- helpers ----------------------------------------------------
__device__ __forceinline__ uint32_t smem_u32(const void* p) {
    uint32_t r;
    asm("{ .reg .u64 t; cvta.to.shared.u64 t, %1; cvt.u32.u64 %0, t; }" : "=r"(r) : "l"(p));
    return r;
}
__device__ __forceinline__ float fast_tanh(float x) {
    float y; asm("tanh.approx.f32 %0, %1;" : "=f"(y) : "f"(x)); return y;
}
__device__ __forceinline__ void hmma(float c[4], const uint32_t a[4], const uint32_t b[2]) {
    asm volatile("mma.sync.aligned.m16n8k16.row.col.f32.bf16.bf16.f32 "
        "{%0,%1,%2,%3}, {%4,%5,%6,%7}, {%8,%9}, {%0,%1,%2,%3};"
        : "+f"(c[0]), "+f"(c[1]), "+f"(c[2]), "+f"(c[3])
        : "r"(a[0]), "r"(a[1]), "r"(a[2]), "r"(a[3]), "r"(b[0]), "r"(b[1]));
}
// swizzled ldmatrix x4: A frag m16k16
__device__ __forceinline__ void ldsm4_s(uint32_t a[4], const bf16* tb, int rowlen,
                                        int rowbase, int ko, int lane) {
    int row = rowbase + (lane & 15);
    int seg = (ko >> 3) + (lane >> 4);
    uint32_t addr = smem_u32(tb + row * rowlen + ((seg ^ (row & 7)) << 3));
    asm volatile("ldmatrix.sync.aligned.m8n8.x4.shared.b16 {%0,%1,%2,%3}, [%4];"
        : "=r"(a[0]), "=r"(a[1]), "=r"(a[2]), "=r"(a[3]) : "r"(addr));
}
// fused x4: B frags for TWO adjacent n8 blocks (n16): b[0..1]=nf0, b[2..3]=nf1
__device__ __forceinline__ void ldsm4_n16(uint32_t b[4], const bf16* tb, int rowlen,
                                          int rowbase, int ko, int lane) {
    int row = rowbase + ((lane >> 4) << 3) + (lane & 7);
    int seg = (ko >> 3) + ((lane >> 3) & 1);
    uint32_t addr = smem_u32(tb + row * rowlen + ((seg ^ (row & 7)) << 3));
    asm volatile("ldmatrix.sync.aligned.m8n8.x4.shared.b16 {%0,%1,%2,%3}, [%4];"
        : "=r"(b[0]), "=r"(b[1]), "=r"(b[2]), "=r"(b[3]) : "r"(addr));
}
__device__ __forceinline__ void ldsm2_s(uint32_t b[2], const bf16* tb, int rowlen,
                                        int rowbase, int ko, int lane) {
    int row = rowbase + (lane & 7);
    int seg = (ko >> 3) + ((lane >> 3) & 1);
    uint32_t addr = smem_u32(tb + row * rowlen + ((seg ^ (row & 7)) << 3));
    asm volatile("ldmatrix.sync.aligned.m8n8.x2.shared.b16 {%0,%1}, [%2];"
        : "=r"(b[0]), "=r"(b[1]) : "r"(addr));
}
__device__ __forceinline__ void cp16(bf16* s, const bf16* g) {
    uint32_t sa = smem_u32(s);
    asm volatile("cp.async.cg.shared.global [%0], [%1], 16;" :: "r"(sa), "l"(g));
}
#define CP_COMMIT() asm volatile("cp.async.commit_group;" ::: "memory")
#define CP_WAIT(n) asm volatile("cp.async.wait_group %0;" :: "n"(n) : "memory")

// async-load [ROWS x SEGS*8] bf16 tile, swizzled
template <int ROWS, int SEGS>
__device__ __forceinline__ void ld_sw(bf16* dst, const bf16* __restrict__ src,
                                      size_t row0, int ld, int k0, int tid) {
#pragma unroll
    for (int i = tid; i < ROWS * SEGS; i += 256) {
        int r = i / SEGS, c = i % SEGS;
        cp16(dst + r * SEGS * 8 + ((c ^ (r & 7)) << 3),
             src + (row0 + (size_t)r) * (size_t)ld + k0 + c * 8);
    }
}

// warp-parallel acquire poll on cnt flags (cnt power of 2); all threads call
__device__ __forceinline__ void wait_flags(volatile unsigned* fl, int cnt,
                                           unsigned tgt, int lane) {
    const unsigned* p = (const unsigned*)(fl + (lane & (cnt - 1)) * 32);
    unsigned v;
    do {
        asm volatile("ld.acquire.gpu.u32 %0, [%1];" : "=r"(v) : "l"(p) : "memory");
    } while (__any_sync(0xffffffffu, (int)(v - tgt) < 0));
}
__device__ __forceinline__ void publish(volatile unsigned* fl, unsigned val) {
    __threadfence();
    asm volatile("st.release.gpu.u32 [%0], %1;" :: "l"((unsigned*)fl), "r"(val) : "memory");
}

// ---------------- prep kernels ----------------------------------------------
__global__ void split_kernel(const float* __restrict__ x, bf16* __restrict__ h,
                             bf16* __restrict__ l, size_t n) {
    size_t i = (size_t)blockIdx.x * 256 + threadIdx.x;
    if (i < n) {
        float v = x[i];
        bf16 a = __float2bfloat16(v);
        h[i] = a;
        l[i] = __float2bfloat16(v - __bfloat162float(a));
    }
}
__global__ void transpose_split(const float* __restrict__ W, bf16* __restrict__ Th,
                                bf16* __restrict__ Tl, int K, int N) {
    int idx = blockIdx.x * 256 + threadIdx.x;
    if (idx < N * K) {
        int n = idx / K, k = idx % K;
        float v = W[k * N + n];
        bf16 a = __float2bfloat16(v);
        Th[idx] = a;
        Tl[idx] = __float2bfloat16(v - __bfloat162float(a));
    }
}

// ---------------- phase-1 GEMM: out = act(A @ W^T + bias) -------------------
#define P1_AH 0
#define P1_AL 8192
#define P1_BH 16384
#define P1_BL 24576
#define P1_BUF 32768
#define P1_SMEM (2 * P1_BUF * 2)

__global__ __launch_bounds__(256) void ff_mma(
    const bf16* __restrict__ Ah, const bf16* __restrict__ Al,
    const bf16* __restrict__ Bh, const bf16* __restrict__ Bl,
    const float* __restrict__ bias, float* __restrict__ outF,
    bf16* __restrict__ outH, bf16* __restrict__ outL,
    int K, int N, int relu_split)
{
    extern __shared__ bf16 sm[];
    bf16* buf[2] = {sm, sm + P1_BUF};
    const int tid = threadIdx.x, lane = tid & 31, wid = tid >> 5;
    const int wm = wid & 3, wn = wid >> 2;
    const size_t rowBase = (size_t)blockIdx.y * 128;
    const int colBase = blockIdx.x * 128;
    const int nch = K / 64;

    float acc[2][8][4];
#pragma unroll
    for (int i = 0; i < 2; i++)
#pragma unroll
        for (int j = 0; j < 8; j++)
#pragma unroll
            for (int q = 0; q < 4; q++) acc[i][j][q] = 0.f;

    ld_sw<128, 8>(buf[0] + P1_AH, Ah, rowBase, K, 0, tid);
    ld_sw<128, 8>(buf[0] + P1_AL, Al, rowBase, K, 0, tid);
    ld_sw<128, 8>(buf[0] + P1_BH, Bh, (size_t)colBase, K, 0, tid);
    ld_sw<128, 8>(buf[0] + P1_BL, Bl, (size_t)colBase, K, 0, tid);
    CP_COMMIT();

    for (int kc = 0; kc < nch; kc++) {
        if (kc < nch - 1) {
            bf16* nb = buf[(kc + 1) & 1];
            int k0 = (kc + 1) * 64;
            ld_sw<128, 8>(nb + P1_AH, Ah, rowBase, K, k0, tid);
            ld_sw<128, 8>(nb + P1_AL, Al, rowBase, K, k0, tid);
            ld_sw<128, 8>(nb + P1_BH, Bh, (size_t)colBase, K, k0, tid);
            ld_sw<128, 8>(nb + P1_BL, Bl, (size_t)colBase, K, k0, tid);
            CP_COMMIT();
            CP_WAIT(1);
        } else {
            CP_WAIT(0);
        }
        __syncthreads();
        bf16* cb = buf[kc & 1];
#pragma unroll
        for (int ks = 0; ks < 4; ks++) {
            int ko = ks * 16;
            uint32_t ah[2][4], al[2][4];
#pragma unroll
            for (int mf = 0; mf < 2; mf++) {
                ldsm4_s(ah[mf], cb + P1_AH, 64, wm * 32 + mf * 16, ko, lane);
                ldsm4_s(al[mf], cb + P1_AL, 64, wm * 32 + mf * 16, ko, lane);
            }
#pragma unroll
            for (int nf = 0; nf < 8; nf++) {
                uint32_t bh[2], bl[2];
                ldsm2_s(bh, cb + P1_BH, 64, wn * 64 + nf * 8, ko, lane);
                ldsm2_s(bl, cb + P1_BL, 64, wn * 64 + nf * 8, ko, lane);
#pragma unroll
                for (int mf = 0; mf < 2; mf++) {
                    hmma(acc[mf][nf], ah[mf], bh);
                    hmma(acc[mf][nf], ah[mf], bl);
                    hmma(acc[mf][nf], al[mf], bh);
                }
            }
        }
        __syncthreads();
    }

#pragma unroll
    for (int mf = 0; mf < 2; mf++) {
#pragma unroll
        for (int nf = 0; nf < 8; nf++) {
            int cg = colBase + wn * 64 + nf * 8 + (lane & 3) * 2;
            float b0 = bias[cg], b1 = bias[cg + 1];
#pragma unroll
            for (int half = 0; half < 2; half++) {
                size_t rg = rowBase + wm * 32 + mf * 16 + (lane >> 2) + half * 8;
                float v0 = acc[mf][nf][half * 2] + b0;
                float v1 = acc[mf][nf][half * 2 + 1] + b1;
                if (relu_split) {
                    v0 = fmaxf(v0, 0.f);
                    v1 = fmaxf(v1, 0.f);
                    __nv_bfloat162 hv, lv;
                    hv.x = __float2bfloat16(v0);
                    hv.y = __float2bfloat16(v1);
                    lv.x = __float2bfloat16(v0 - __bfloat162float(hv.x));
                    lv.y = __float2bfloat16(v1 - __bfloat162float(hv.y));
                    *(__nv_bfloat162*)&outH[rg * N + cg] = hv;
                    *(__nv_bfloat162*)&outL[rg * N + cg] = lv;
                } else {
                    *(float2*)&outF[rg * N + cg] = make_float2(v0, v1);
                }
            }
        }
    }
}

// ---------------- persistent recurrence: 8 groups x 16 CTAs -----------------
// R12 structure; single change: phase-A K-chunk 256 (3 stages x 32KB),
// halving syncthreads and pipeline turns in phase A.
#define RW_H 0
#define RW_L 32768
#define RD 65536
#define PB_AH 0
#define PB_AL 4096
#define PB_WH 8192
#define PB_WL 16384
#define PB_STAGE 24576
#define PA_ST 16384
#define R_SMEM ((65536 + 2 * 24576) * 2)

__global__ __launch_bounds__(256) void recurrence(
    const float* __restrict__ b1h, const float* __restrict__ b2h,
    const int* __restrict__ lens, float* __restrict__ out)
{
    extern __shared__ bf16 sm[];
    bf16* smWH = sm + RW_H;
    bf16* smWL = sm + RW_L;
    const int tid = threadIdx.x, lane = tid & 31, wid = tid >> 5;
    const int wm = wid & 1, wn = wid >> 1;  // 2m x 4n warps
    const int cta = blockIdx.x;
    const int grp = cta >> 4;
    const int slot = cta & 15;
    const size_t rbase = (size_t)grp * 32;
    const int cbaseA = slot * 32;
    const int cbaseB = slot * 64;

    const unsigned baseH = g_fh[grp][slot * 32];
    const unsigned baseI = g_fi[grp][slot * 32];

    // zero h state by COLUMN ownership
    for (int i = tid; i < 32 * 32; i += 256) {
        int r = i >> 5, c = (i & 31) * 2;
        size_t j = (rbase + r) * H_ + cbaseB + c;
        *(__nv_bfloat162*)&g_hh[j] = __nv_bfloat162{__float2bfloat16(0.f), __float2bfloat16(0.f)};
        *(__nv_bfloat162*)&g_hl[j] = __nv_bfloat162{__float2bfloat16(0.f), __float2bfloat16(0.f)};
    }
    __syncthreads();
    if (tid == 0) publish(&g_fh[grp][slot * 32], baseH + 1);

    // resident phase-A weights
    for (int i = tid; i < 32 * 128; i += 256) {
        int r = i >> 7, c = i & 127;
        int d = r * 1024 + ((c ^ (r & 7)) << 3);
        *(uint4*)(smWH + d) = *(const uint4*)&g_w1hTh[(size_t)(cbaseA + r) * H_ + c * 8];
        *(uint4*)(smWL + d) = *(const uint4*)&g_w1hTl[(size_t)(cbaseA + r) * H_ + c * 8];
    }
    __syncthreads();

    const size_t rg0 = rbase + wm * 16 + (lane >> 2);
    const size_t rg1 = rg0 + 8;
    const int len0 = lens[rg0], len1 = lens[rg1];
    const int cgA = cbaseA + wn * 8 + (lane & 3) * 2;
    const float pb1_0 = b1h[cgA], pb1_1 = b1h[cgA + 1];
    float pb2[2][2];
#pragma unroll
    for (int nf = 0; nf < 2; nf++) {
        int cg = cbaseB + wn * 16 + nf * 8 + (lane & 3) * 2;
        pb2[nf][0] = b2h[cg];
        pb2[nf][1] = b2h[cg + 1];
    }
    float h_prev[2][4];
#pragma unroll
    for (int nf = 0; nf < 2; nf++)
#pragma unroll
        for (int q = 0; q < 4; q++) h_prev[nf][q] = 0.f;

    for (int t = 0; t < S_; t++) {
        const unsigned tgtH = baseH + (unsigned)t + 1;
        const unsigned tgtI = baseI + (unsigned)t + 1;
        const int par = t & 1;
        const bf16* ihr = g_ih[par];
        const bf16* ilr = g_il[par];

        // xh prefetch (flag-independent)
        float2 xv[2][2];
#pragma unroll
        for (int nf = 0; nf < 2; nf++) {
            int cg = cbaseB + wn * 16 + nf * 8 + (lane & 3) * 2;
            xv[nf][0] = *(const float2*)&g_xh[(rg0 * S_ + t) * H_ + cg];
            xv[nf][1] = *(const float2*)&g_xh[(rg1 * S_ + t) * H_ + cg];
        }

        // ---- phase A prologue: issue 256-wide chunks 0..2 into 3 stages ----
#pragma unroll
        for (int p = 0; p < 3; p++) {
            wait_flags(g_fh[grp] + 4 * p * 32, 4, tgtH, lane);
            bf16* hs = sm + RD + p * PA_ST;
            ld_sw<32, 32>(hs, g_hh, rbase, H_, p * 256, tid);
            ld_sw<32, 32>(hs + 8192, g_hl, rbase, H_, p * 256, tid);
            CP_COMMIT();
        }

        // ================= phase A (4 chunks of K=256) =================
        float accA[3][4];
#pragma unroll
        for (int i = 0; i < 3; i++)
#pragma unroll
            for (int q = 0; q < 4; q++) accA[i][q] = 0.f;

#pragma unroll
        for (int kc = 0; kc < 4; kc++) {
            if (kc <= 1) { CP_WAIT(2); }
            else if (kc == 2) { CP_WAIT(1); }
            else { CP_WAIT(0); }
            __syncthreads();
            bf16* hs = sm + RD + (kc % 3) * PA_ST;
#pragma unroll
            for (int ks = 0; ks < 16; ks++) {
                int ko = ks * 16;
                uint32_t ah[4], al[4], bh[2], bl[2];
                ldsm4_s(ah, hs, 256, wm * 16, ko, lane);
                ldsm4_s(al, hs + 8192, 256, wm * 16, ko, lane);
                ldsm2_s(bh, smWH, 1024, wn * 8, kc * 256 + ko, lane);
                ldsm2_s(bl, smWL, 1024, wn * 8, kc * 256 + ko, lane);
                hmma(accA[0], ah, bh);
                hmma(accA[1], ah, bl);
                hmma(accA[2], al, bh);
            }
            __syncthreads();
            if (kc == 0) {   // issue chunk 3 into freed stage 0
                wait_flags(g_fh[grp] + 12 * 32, 4, tgtH, lane);
                bf16* ns = sm + RD;
                ld_sw<32, 32>(ns, g_hh, rbase, H_, 3 * 256, tid);
                ld_sw<32, 32>(ns + 8192, g_hl, rbase, H_, 3 * 256, tid);
                CP_COMMIT();
            }
        }

        // ---- epilogue A: relu + split -> inter (buffer t&1) ----
#pragma unroll
        for (int half = 0; half < 2; half++) {
            size_t rg = (half == 0) ? rg0 : rg1;
            float v0 = fmaxf(accA[0][half * 2] + accA[1][half * 2] +
                             accA[2][half * 2] + pb1_0, 0.f);
            float v1 = fmaxf(accA[0][half * 2 + 1] + accA[1][half * 2 + 1] +
                             accA[2][half * 2 + 1] + pb1_1, 0.f);
            __nv_bfloat162 hv, lv;
            hv.x = __float2bfloat16(v0);
            hv.y = __float2bfloat16(v1);
            lv.x = __float2bfloat16(v0 - __bfloat162float(hv.x));
            lv.y = __float2bfloat16(v1 - __bfloat162float(hv.y));
            *(__nv_bfloat162*)&g_ih[par][rg * HH_ + cgA] = hv;
            *(__nv_bfloat162*)&g_il[par][rg * HH_ + cgA] = lv;
        }
        __syncthreads();
        if (tid == 0) publish(&g_fi[grp][slot * 32], tgtI);

        // W2 prefetch chunks 0,1 (flag-independent)
        ld_sw<64, 16>(sm + RD + PB_WH, g_w2hTh, (size_t)cbaseB, HH_, 0, tid);
        ld_sw<64, 16>(sm + RD + PB_WL, g_w2hTl, (size_t)cbaseB, HH_, 0, tid);
        CP_COMMIT();
        ld_sw<64, 16>(sm + RD + PB_STAGE + PB_WH, g_w2hTh, (size_t)cbaseB, HH_, 128, tid);
        ld_sw<64, 16>(sm + RD + PB_STAGE + PB_WL, g_w2hTl, (size_t)cbaseB, HH_, 128, tid);
        CP_COMMIT();

        // wait inter cols 0..255 (CTAs 0..7), issue inter chunks 0,1
        wait_flags(g_fi[grp], 8, tgtI, lane);
        ld_sw<32, 16>(sm + RD + PB_AH, ihr, rbase, HH_, 0, tid);
        ld_sw<32, 16>(sm + RD + PB_AL, ilr, rbase, HH_, 0, tid);
        CP_COMMIT();
        ld_sw<32, 16>(sm + RD + PB_STAGE + PB_AH, ihr, rbase, HH_, 128, tid);
        ld_sw<32, 16>(sm + RD + PB_STAGE + PB_AL, ilr, rbase, HH_, 128, tid);
        CP_COMMIT();

        // ================= phase B =================
        float accB[2][3][4];
#pragma unroll
        for (int nf = 0; nf < 2; nf++)
#pragma unroll
            for (int i = 0; i < 3; i++)
#pragma unroll
                for (int q = 0; q < 4; q++) accB[nf][i][q] = 0.f;

#pragma unroll
        for (int kc = 0; kc < 4; kc++) {
            if (kc < 3) { CP_WAIT(1); } else { CP_WAIT(0); }
            __syncthreads();
            bf16* cb = sm + RD + (kc & 1) * PB_STAGE;
#pragma unroll
            for (int ks = 0; ks < 8; ks++) {
                int ko = ks * 16;
                uint32_t ah[4], al[4], bh4[4], bl4[4];
                ldsm4_s(ah, cb + PB_AH, 128, wm * 16, ko, lane);
                ldsm4_s(al, cb + PB_AL, 128, wm * 16, ko, lane);
                ldsm4_n16(bh4, cb + PB_WH, 128, wn * 16, ko, lane);
                ldsm4_n16(bl4, cb + PB_WL, 128, wn * 16, ko, lane);
#pragma unroll
                for (int nf = 0; nf < 2; nf++) {
                    hmma(accB[nf][0], ah, bh4 + 2 * nf);
                    hmma(accB[nf][1], ah, bl4 + 2 * nf);
                    hmma(accB[nf][2], al, bh4 + 2 * nf);
                }
            }
            __syncthreads();
            if (kc < 2) {
                wait_flags(g_fi[grp] + (8 + 4 * kc) * 32, 4, tgtI, lane);
                bf16* ns = sm + RD + (kc & 1) * PB_STAGE;
                int k0 = (kc + 2) * 128;
                ld_sw<32, 16>(ns + PB_AH, ihr, rbase, HH_, k0, tid);
                ld_sw<32, 16>(ns + PB_AL, ilr, rbase, HH_, k0, tid);
                ld_sw<64, 16>(ns + PB_WH, g_w2hTh, (size_t)cbaseB, HH_, k0, tid);
                ld_sw<64, 16>(ns + PB_WL, g_w2hTl, (size_t)cbaseB, HH_, k0, tid);
                CP_COMMIT();
            }
        }

        // ---- epilogue B: compute + h-state stores FIRST, publish, then out --
        float res[2][2][2];
#pragma unroll
        for (int nf = 0; nf < 2; nf++) {
            int cg = cbaseB + wn * 16 + nf * 8 + (lane & 3) * 2;
#pragma unroll
            for (int half = 0; half < 2; half++) {
                bool on = t < ((half == 0) ? len0 : len1);
                size_t rg = (half == 0) ? rg0 : rg1;
                float v0, v1;
                if (on) {
                    float s0 = accB[nf][0][half * 2] + accB[nf][1][half * 2] +
                               accB[nf][2][half * 2];
                    float s1 = accB[nf][0][half * 2 + 1] + accB[nf][1][half * 2 + 1] +
                               accB[nf][2][half * 2 + 1];
                    v0 = fast_tanh(xv[nf][half].x + s0 + pb2[nf][0]);
                    v1 = fast_tanh(xv[nf][half].y + s1 + pb2[nf][1]);
                    h_prev[nf][half * 2] = v0;
                    h_prev[nf][half * 2 + 1] = v1;
                    __nv_bfloat162 hv, lv;
                    hv.x = __float2bfloat16(v0);
                    hv.y = __float2bfloat16(v1);
                    lv.x = __float2bfloat16(v0 - __bfloat162float(hv.x));
                    lv.y = __float2bfloat16(v1 - __bfloat162float(hv.y));
                    *(__nv_bfloat162*)&g_hh[rg * H_ + cg] = hv;
                    *(__nv_bfloat162*)&g_hl[rg * H_ + cg] = lv;
                } else {
                    v0 = h_prev[nf][half * 2];
                    v1 = h_prev[nf][half * 2 + 1];
                }
                res[nf][half][0] = v0;
                res[nf][half][1] = v1;
            }
        }
        __syncthreads();
        if (tid == 0) publish(&g_fh[grp][slot * 32], baseH + (unsigned)t + 2);
        // out writes off the critical path, streaming
#pragma unroll
        for (int nf = 0; nf < 2; nf++) {
            int cg = cbaseB + wn * 16 + nf * 8 + (lane & 3) * 2;
#pragma unroll
            for (int half = 0; half < 2; half++) {
                size_t rg = (half == 0) ? rg0 : rg1;
                __stcs((float2*)&out[(rg * S_ + t) * H_ + cg],
                       make_float2(res[nf][half][0], res[nf][half][1]));
            }
        }
    }
}

// ---------------- launcher --------------------------------------------------
extern "C" void kernel_launch(void* const* d_in, const int* in_sizes, int n_in,
                              void* d_out, int out_size) {
    const float* seq = (const float*)d_in[0];
    const int* lens  = (const int*)d_in[1];
    const float* w1x = (const float*)d_in[2];
    const float* b1x = (const float*)d_in[3];
    const float* w2x = (const float*)d_in[4];
    const float* b2x = (const float*)d_in[5];
    const float* w1h = (const float*)d_in[6];
    const float* b1h = (const float*)d_in[7];
    const float* w2h = (const float*)d_in[8];
    const float* b2h = (const float*)d_in[9];
    float* out = (float*)d_out;

    bf16 *seqh, *seql, *tmph, *tmpl;
    bf16 *w1xh, *w1xl, *w2xh, *w2xl, *w1hh, *w1hl, *w2hh, *w2hl;
    float* xh;
    cudaGetSymbolAddress((void**)&seqh, g_seqh);
    cudaGetSymbolAddress((void**)&seql, g_seql);
    cudaGetSymbolAddress((void**)&tmph, g_tmph);
    cudaGetSymbolAddress((void**)&tmpl, g_tmpl);
    cudaGetSymbolAddress((void**)&xh, g_xh);
    cudaGetSymbolAddress((void**)&w1xh, g_w1xTh);
    cudaGetSymbolAddress((void**)&w1xl, g_w1xTl);
    cudaGetSymbolAddress((void**)&w2xh, g_w2xTh);
    cudaGetSymbolAddress((void**)&w2xl, g_w2xTl);
    cudaGetSymbolAddress((void**)&w1hh, g_w1hTh);
    cudaGetSymbolAddress((void**)&w1hl, g_w1hTl);
    cudaGetSymbolAddress((void**)&w2hh, g_w2hTh);
    cudaGetSymbolAddress((void**)&w2hl, g_w2hTl);

    cudaFuncSetAttribute(ff_mma, cudaFuncAttributeMaxDynamicSharedMemorySize, P1_SMEM);
    cudaFuncSetAttribute(recurrence, cudaFuncAttributeMaxDynamicSharedMemorySize, R_SMEM);

    size_t nseq = (size_t)MTOK * E_;
    split_kernel<<<(unsigned)((nseq + 255) / 256), 256>>>(seq, seqh, seql, nseq);
    transpose_split<<<(E_ * HH_ + 255) / 256, 256>>>(w1x, w1xh, w1xl, E_, HH_);
    transpose_split<<<(HH_ * H_ + 255) / 256, 256>>>(w2x, w2xh, w2xl, HH_, H_);
    transpose_split<<<(H_ * HH_ + 255) / 256, 256>>>(w1h, w1hh, w1hl, H_, HH_);
    transpose_split<<<(HH_ * H_ + 255) / 256, 256>>>(w2h, w2hh, w2hl, HH_, H_);

    ff_mma<<<dim3(HH_ / 128, MTOK / 128), 256, P1_SMEM>>>(
        seqh, seql, w1xh, w1xl, b1x, nullptr, tmph, tmpl, E_, HH_, 1);
    ff_mma<<<dim3(H_ / 128, MTOK / 128), 256, P1_SMEM>>>(
        tmph, tmpl, w2xh, w2xl, b2x, xh, nullptr, nullptr, HH_, H_, 0);

    recurrence<<<128, 256, R_SMEM>>>(b1h, b2h, lens, out);
}

// round 14
// speedup vs baseline: 1.0803x; 1.0105x over previous
#include <cuda_runtime.h>
#include <cuda_bf16.h>
#include <cstdint>

#define B_ 256
#define S_ 512
#define E_ 512
#define H_ 1024
#define HH_ 512
#define MTOK (B_ * S_)

typedef __nv_bfloat16 bf16;

// ---------------- device-global scratch ------------------------------------
__device__ bf16 g_seqh[(size_t)MTOK * E_];
__device__ bf16 g_seql[(size_t)MTOK * E_];
__device__ bf16 g_tmph[(size_t)MTOK * HH_];
__device__ bf16 g_tmpl[(size_t)MTOK * HH_];
__device__ float g_xh[(size_t)MTOK * H_];
__device__ bf16 g_w1xTh[HH_ * E_], g_w1xTl[HH_ * E_];   // [N,K]
__device__ bf16 g_w2xTh[H_ * HH_], g_w2xTl[H_ * HH_];
__device__ bf16 g_w1hTh[HH_ * H_], g_w1hTl[HH_ * H_];
__device__ bf16 g_w2hTh[H_ * HH_], g_w2hTl[H_ * HH_];
__device__ bf16 g_hh[B_ * H_], g_hl[B_ * H_];
__device__ bf16 g_ih[2][B_ * HH_], g_il[2][B_ * HH_];   // inter double-buffered
// monotonic per-CTA flags (128B stride per flag)
__device__ volatile unsigned g_fh[8][16 * 32];
__device__ volatile unsigned g_fi[8][16 * 32];

// ---------------- helpers ----------------------------------------------------
__device__ __forceinline__ uint32_t smem_u32(const void* p) {
    uint32_t r;
    asm("{ .reg .u64 t; cvta.to.shared.u64 t, %1; cvt.u32.u64 %0, t; }" : "=r"(r) : "l"(p));
    return r;
}
__device__ __forceinline__ float fast_tanh(float x) {
    float y; asm("tanh.approx.f32 %0, %1;" : "=f"(y) : "f"(x)); return y;
}
__device__ __forceinline__ void hmma(float c[4], const uint32_t a[4], const uint32_t b[2]) {
    asm volatile("mma.sync.aligned.m16n8k16.row.col.f32.bf16.bf16.f32 "
        "{%0,%1,%2,%3}, {%4,%5,%6,%7}, {%8,%9}, {%0,%1,%2,%3};"
        : "+f"(c[0]), "+f"(c[1]), "+f"(c[2]), "+f"(c[3])
        : "r"(a[0]), "r"(a[1]), "r"(a[2]), "r"(a[3]), "r"(b[0]), "r"(b[1]));
}
// swizzled ldmatrix x4: A frag m16k16
__device__ __forceinline__ void ldsm4_s(uint32_t a[4], const bf16* tb, int rowlen,
                                        int rowbase, int ko, int lane) {
    int row = rowbase + (lane & 15);
    int seg = (ko >> 3) + (lane >> 4);
    uint32_t addr = smem_u32(tb + row * rowlen + ((seg ^ (row & 7)) << 3));
    asm volatile("ldmatrix.sync.aligned.m8n8.x4.shared.b16 {%0,%1,%2,%3}, [%4];"
        : "=r"(a[0]), "=r"(a[1]), "=r"(a[2]), "=r"(a[3]) : "r"(addr));
}
// fused x4: B frags for TWO adjacent n8 blocks (n16): b[0..1]=nf0, b[2..3]=nf1
__device__ __forceinline__ void ldsm4_n16(uint32_t b[4], const bf16* tb, int rowlen,
                                          int rowbase, int ko, int lane) {
    int row = rowbase + ((lane >> 4) << 3) + (lane & 7);
    int seg = (ko >> 3) + ((lane >> 3) & 1);
    uint32_t addr = smem_u32(tb + row * rowlen + ((seg ^ (row & 7)) << 3));
    asm volatile("ldmatrix.sync.aligned.m8n8.x4.shared.b16 {%0,%1,%2,%3}, [%4];"
        : "=r"(b[0]), "=r"(b[1]), "=r"(b[2]), "=r"(b[3]) : "r"(addr));
}
__device__ __forceinline__ void ldsm2_s(uint32_t b[2], const bf16* tb, int rowlen,
                                        int rowbase, int ko, int lane) {
    int row = rowbase + (lane & 7);
    int seg = (ko >> 3) + ((lane >> 3) & 1);
    uint32_t addr = smem_u32(tb + row * rowlen + ((seg ^ (row & 7)) << 3));
    asm volatile("ldmatrix.sync.aligned.m8n8.x2.shared.b16 {%0,%1}, [%2];"
        : "=r"(b[0]), "=r"(b[1]) : "r"(addr));
}
__device__ __forceinline__ void cp16(bf16* s, const bf16* g) {
    uint32_t sa = smem_u32(s);
    asm volatile("cp.async.cg.shared.global [%0], [%1], 16;" :: "r"(sa), "l"(g));
}
#define CP_COMMIT() asm volatile("cp.async.commit_group;" ::: "memory")
#define CP_WAIT(n) asm volatile("cp.async.wait_group %0;" :: "n"(n) : "memory")

// async-load [ROWS x SEGS*8] bf16 tile, swizzled
template <int ROWS, int SEGS>
__device__ __forceinline__ void ld_sw(bf16* dst, const bf16* __restrict__ src,
                                      size_t row0, int ld, int k0, int tid) {
#pragma unroll
    for (int i = tid; i < ROWS * SEGS; i += 256) {
        int r = i / SEGS, c = i % SEGS;
        cp16(dst + r * SEGS * 8 + ((c ^ (r & 7)) << 3),
             src + (row0 + (size_t)r) * (size_t)ld + k0 + c * 8);
    }
}

// warp-parallel acquire poll on cnt flags (cnt power of 2); all threads call
__device__ __forceinline__ void wait_flags(volatile unsigned* fl, int cnt,
                                           unsigned tgt, int lane) {
    const unsigned* p = (const unsigned*)(fl + (lane & (cnt - 1)) * 32);
    unsigned v;
    do {
        asm volatile("ld.acquire.gpu.u32 %0, [%1];" : "=r"(v) : "l"(p) : "memory");
    } while (__any_sync(0xffffffffu, (int)(v - tgt) < 0));
}
__device__ __forceinline__ void publish(volatile unsigned* fl, unsigned val) {
    __threadfence();
    asm volatile("st.release.gpu.u32 [%0], %1;" :: "l"((unsigned*)fl), "r"(val) : "memory");
}

// ---------------- prep kernels ----------------------------------------------
__global__ void split_kernel(const float* __restrict__ x, bf16* __restrict__ h,
                             bf16* __restrict__ l, size_t n) {
    size_t i = (size_t)blockIdx.x * 256 + threadIdx.x;
    if (i < n) {
        float v = x[i];
        bf16 a = __float2bfloat16(v);
        h[i] = a;
        l[i] = __float2bfloat16(v - __bfloat162float(a));
    }
}
__global__ void transpose_split(const float* __restrict__ W, bf16* __restrict__ Th,
                                bf16* __restrict__ Tl, int K, int N) {
    int idx = blockIdx.x * 256 + threadIdx.x;
    if (idx < N * K) {
        int n = idx / K, k = idx % K;
        float v = W[k * N + n];
        bf16 a = __float2bfloat16(v);
        Th[idx] = a;
        Tl[idx] = __float2bfloat16(v - __bfloat162float(a));
    }
}

// ---------------- phase-1 GEMM: out = act(A @ W^T + bias) -------------------
#define P1_AH 0
#define P1_AL 8192
#define P1_BH 16384
#define P1_BL 24576
#define P1_BUF 32768
#define P1_SMEM (2 * P1_BUF * 2)

__global__ __launch_bounds__(256) void ff_mma(
    const bf16* __restrict__ Ah, const bf16* __restrict__ Al,
    const bf16* __restrict__ Bh, const bf16* __restrict__ Bl,
    const float* __restrict__ bias, float* __restrict__ outF,
    bf16* __restrict__ outH, bf16* __restrict__ outL,
    int K, int N, int relu_split)
{
    extern __shared__ bf16 sm[];
    bf16* buf[2] = {sm, sm + P1_BUF};
    const int tid = threadIdx.x, lane = tid & 31, wid = tid >> 5;
    const int wm = wid & 3, wn = wid >> 2;
    const size_t rowBase = (size_t)blockIdx.y * 128;
    const int colBase = blockIdx.x * 128;
    const int nch = K / 64;

    float acc[2][8][4];
#pragma unroll
    for (int i = 0; i < 2; i++)
#pragma unroll
        for (int j = 0; j < 8; j++)
#pragma unroll
            for (int q = 0; q < 4; q++) acc[i][j][q] = 0.f;

    ld_sw<128, 8>(buf[0] + P1_AH, Ah, rowBase, K, 0, tid);
    ld_sw<128, 8>(buf[0] + P1_AL, Al, rowBase, K, 0, tid);
    ld_sw<128, 8>(buf[0] + P1_BH, Bh, (size_t)colBase, K, 0, tid);
    ld_sw<128, 8>(buf[0] + P1_BL, Bl, (size_t)colBase, K, 0, tid);
    CP_COMMIT();

    for (int kc = 0; kc < nch; kc++) {
        if (kc < nch - 1) {
            bf16* nb = buf[(kc + 1) & 1];
            int k0 = (kc + 1) * 64;
            ld_sw<128, 8>(nb + P1_AH, Ah, rowBase, K, k0, tid);
            ld_sw<128, 8>(nb + P1_AL, Al, rowBase, K, k0, tid);
            ld_sw<128, 8>(nb + P1_BH, Bh, (size_t)colBase, K, k0, tid);
            ld_sw<128, 8>(nb + P1_BL, Bl, (size_t)colBase, K, k0, tid);
            CP_COMMIT();
            CP_WAIT(1);
        } else {
            CP_WAIT(0);
        }
        __syncthreads();
        bf16* cb = buf[kc & 1];
#pragma unroll
        for (int ks = 0; ks < 4; ks++) {
            int ko = ks * 16;
            uint32_t ah[2][4], al[2][4];
#pragma unroll
            for (int mf = 0; mf < 2; mf++) {
                ldsm4_s(ah[mf], cb + P1_AH, 64, wm * 32 + mf * 16, ko, lane);
                ldsm4_s(al[mf], cb + P1_AL, 64, wm * 32 + mf * 16, ko, lane);
            }
#pragma unroll
            for (int np = 0; np < 4; np++) {
                uint32_t bh4[4], bl4[4];
                ldsm4_n16(bh4, cb + P1_BH, 64, wn * 64 + np * 16, ko, lane);
                ldsm4_n16(bl4, cb + P1_BL, 64, wn * 64 + np * 16, ko, lane);
#pragma unroll
                for (int s = 0; s < 2; s++) {
#pragma unroll
                    for (int mf = 0; mf < 2; mf++) {
                        hmma(acc[mf][np * 2 + s], ah[mf], bh4 + 2 * s);
                        hmma(acc[mf][np * 2 + s], ah[mf], bl4 + 2 * s);
                        hmma(acc[mf][np * 2 + s], al[mf], bh4 + 2 * s);
                    }
                }
            }
        }
        __syncthreads();
    }

#pragma unroll
    for (int mf = 0; mf < 2; mf++) {
#pragma unroll
        for (int nf = 0; nf < 8; nf++) {
            int cg = colBase + wn * 64 + nf * 8 + (lane & 3) * 2;
            float b0 = bias[cg], b1 = bias[cg + 1];
#pragma unroll
            for (int half = 0; half < 2; half++) {
                size_t rg = rowBase + wm * 32 + mf * 16 + (lane >> 2) + half * 8;
                float v0 = acc[mf][nf][half * 2] + b0;
                float v1 = acc[mf][nf][half * 2 + 1] + b1;
                if (relu_split) {
                    v0 = fmaxf(v0, 0.f);
                    v1 = fmaxf(v1, 0.f);
                    __nv_bfloat162 hv, lv;
                    hv.x = __float2bfloat16(v0);
                    hv.y = __float2bfloat16(v1);
                    lv.x = __float2bfloat16(v0 - __bfloat162float(hv.x));
                    lv.y = __float2bfloat16(v1 - __bfloat162float(hv.y));
                    *(__nv_bfloat162*)&outH[rg * N + cg] = hv;
                    *(__nv_bfloat162*)&outL[rg * N + cg] = lv;
                } else {
                    *(float2*)&outF[rg * N + cg] = make_float2(v0, v1);
                }
            }
        }
    }
}

// ---------------- persistent recurrence: 8 groups x 16 CTAs -----------------
// R13 structure; phase A converted to single-sync pipeline (prologue fills 2
// of 3 stages; issue-into-freed-stage happens after the iteration's only sync).
#define RW_H 0
#define RW_L 32768
#define RD 65536
#define PB_AH 0
#define PB_AL 4096
#define PB_WH 8192
#define PB_WL 16384
#define PB_STAGE 24576
#define PA_ST 16384
#define R_SMEM ((65536 + 2 * 24576) * 2)

__global__ __launch_bounds__(256) void recurrence(
    const float* __restrict__ b1h, const float* __restrict__ b2h,
    const int* __restrict__ lens, float* __restrict__ out)
{
    extern __shared__ bf16 sm[];
    bf16* smWH = sm + RW_H;
    bf16* smWL = sm + RW_L;
    const int tid = threadIdx.x, lane = tid & 31, wid = tid >> 5;
    const int wm = wid & 1, wn = wid >> 1;  // 2m x 4n warps
    const int cta = blockIdx.x;
    const int grp = cta >> 4;
    const int slot = cta & 15;
    const size_t rbase = (size_t)grp * 32;
    const int cbaseA = slot * 32;
    const int cbaseB = slot * 64;

    const unsigned baseH = g_fh[grp][slot * 32];
    const unsigned baseI = g_fi[grp][slot * 32];

    // zero h state by COLUMN ownership
    for (int i = tid; i < 32 * 32; i += 256) {
        int r = i >> 5, c = (i & 31) * 2;
        size_t j = (rbase + r) * H_ + cbaseB + c;
        *(__nv_bfloat162*)&g_hh[j] = __nv_bfloat162{__float2bfloat16(0.f), __float2bfloat16(0.f)};
        *(__nv_bfloat162*)&g_hl[j] = __nv_bfloat162{__float2bfloat16(0.f), __float2bfloat16(0.f)};
    }
    __syncthreads();
    if (tid == 0) publish(&g_fh[grp][slot * 32], baseH + 1);

    // resident phase-A weights
    for (int i = tid; i < 32 * 128; i += 256) {
        int r = i >> 7, c = i & 127;
        int d = r * 1024 + ((c ^ (r & 7)) << 3);
        *(uint4*)(smWH + d) = *(const uint4*)&g_w1hTh[(size_t)(cbaseA + r) * H_ + c * 8];
        *(uint4*)(smWL + d) = *(const uint4*)&g_w1hTl[(size_t)(cbaseA + r) * H_ + c * 8];
    }
    __syncthreads();

    const size_t rg0 = rbase + wm * 16 + (lane >> 2);
    const size_t rg1 = rg0 + 8;
    const int len0 = lens[rg0], len1 = lens[rg1];
    const int cgA = cbaseA + wn * 8 + (lane & 3) * 2;
    const float pb1_0 = b1h[cgA], pb1_1 = b1h[cgA + 1];
    float pb2[2][2];
#pragma unroll
    for (int nf = 0; nf < 2; nf++) {
        int cg = cbaseB + wn * 16 + nf * 8 + (lane & 3) * 2;
        pb2[nf][0] = b2h[cg];
        pb2[nf][1] = b2h[cg + 1];
    }
    float h_prev[2][4];
#pragma unroll
    for (int nf = 0; nf < 2; nf++)
#pragma unroll
        for (int q = 0; q < 4; q++) h_prev[nf][q] = 0.f;

    for (int t = 0; t < S_; t++) {
        const unsigned tgtH = baseH + (unsigned)t + 1;
        const unsigned tgtI = baseI + (unsigned)t + 1;
        const int par = t & 1;
        const bf16* ihr = g_ih[par];
        const bf16* ilr = g_il[par];

        // xh prefetch (flag-independent)
        float2 xv[2][2];
#pragma unroll
        for (int nf = 0; nf < 2; nf++) {
            int cg = cbaseB + wn * 16 + nf * 8 + (lane & 3) * 2;
            xv[nf][0] = *(const float2*)&g_xh[(rg0 * S_ + t) * H_ + cg];
            xv[nf][1] = *(const float2*)&g_xh[(rg1 * S_ + t) * H_ + cg];
        }

        // ---- phase A prologue: fill 2 of 3 stages (K-chunks of 256) ----
#pragma unroll
        for (int p = 0; p < 2; p++) {
            wait_flags(g_fh[grp] + 4 * p * 32, 4, tgtH, lane);
            bf16* hs = sm + RD + p * PA_ST;
            ld_sw<32, 32>(hs, g_hh, rbase, H_, p * 256, tid);
            ld_sw<32, 32>(hs + 8192, g_hl, rbase, H_, p * 256, tid);
            CP_COMMIT();
        }

        // ================= phase A (4 chunks of K=256, ONE sync each) ======
        float accA[3][4];
#pragma unroll
        for (int i = 0; i < 3; i++)
#pragma unroll
            for (int q = 0; q < 4; q++) accA[i][q] = 0.f;

#pragma unroll
        for (int kc = 0; kc < 4; kc++) {
            if (kc < 3) { CP_WAIT(1); } else { CP_WAIT(0); }
            __syncthreads();
            if (kc < 2) {   // issue chunk kc+2 into stage freed last iteration
                int c = kc + 2;
                wait_flags(g_fh[grp] + 4 * c * 32, 4, tgtH, lane);
                bf16* ns = sm + RD + (c % 3) * PA_ST;
                ld_sw<32, 32>(ns, g_hh, rbase, H_, c * 256, tid);
                ld_sw<32, 32>(ns + 8192, g_hl, rbase, H_, c * 256, tid);
                CP_COMMIT();
            }
            bf16* hs = sm + RD + (kc % 3) * PA_ST;
#pragma unroll
            for (int ks = 0; ks < 16; ks++) {
                int ko = ks * 16;
                uint32_t ah[4], al[4], bh[2], bl[2];
                ldsm4_s(ah, hs, 256, wm * 16, ko, lane);
                ldsm4_s(al, hs + 8192, 256, wm * 16, ko, lane);
                ldsm2_s(bh, smWH, 1024, wn * 8, kc * 256 + ko, lane);
                ldsm2_s(bl, smWL, 1024, wn * 8, kc * 256 + ko, lane);
                hmma(accA[0], ah, bh);
                hmma(accA[1], ah, bl);
                hmma(accA[2], al, bh);
            }
        }

        // ---- epilogue A: relu + split -> inter (buffer t&1) ----
#pragma unroll
        for (int half = 0; half < 2; half++) {
            size_t rg = (half == 0) ? rg0 : rg1;
            float v0 = fmaxf(accA[0][half * 2] + accA[1][half * 2] +
                             accA[2][half * 2] + pb1_0, 0.f);
            float v1 = fmaxf(accA[0][half * 2 + 1] + accA[1][half * 2 + 1] +
                             accA[2][half * 2 + 1] + pb1_1, 0.f);
            __nv_bfloat162 hv, lv;
            hv.x = __float2bfloat16(v0);
            hv.y = __float2bfloat16(v1);
            lv.x = __float2bfloat16(v0 - __bfloat162float(hv.x));
            lv.y = __float2bfloat16(v1 - __bfloat162float(hv.y));
            *(__nv_bfloat162*)&g_ih[par][rg * HH_ + cgA] = hv;
            *(__nv_bfloat162*)&g_il[par][rg * HH_ + cgA] = lv;
        }
        __syncthreads();   // all warps done with PA stages + inter stores done
        if (tid == 0) publish(&g_fi[grp][slot * 32], tgtI);

        // W2 prefetch chunks 0,1 (flag-independent)
        ld_sw<64, 16>(sm + RD + PB_WH, g_w2hTh, (size_t)cbaseB, HH_, 0, tid);
        ld_sw<64, 16>(sm + RD + PB_WL, g_w2hTl, (size_t)cbaseB, HH_, 0, tid);
        CP_COMMIT();
        ld_sw<64, 16>(sm + RD + PB_STAGE + PB_WH, g_w2hTh, (size_t)cbaseB, HH_, 128, tid);
        ld_sw<64, 16>(sm + RD + PB_STAGE + PB_WL, g_w2hTl, (size_t)cbaseB, HH_, 128, tid);
        CP_COMMIT();

        // wait inter cols 0..255 (CTAs 0..7), issue inter chunks 0,1
        wait_flags(g_fi[grp], 8, tgtI, lane);
        ld_sw<32, 16>(sm + RD + PB_AH, ihr, rbase, HH_, 0, tid);
        ld_sw<32, 16>(sm + RD + PB_AL, ilr, rbase, HH_, 0, tid);
        CP_COMMIT();
        ld_sw<32, 16>(sm + RD + PB_STAGE + PB_AH, ihr, rbase, HH_, 128, tid);
        ld_sw<32, 16>(sm + RD + PB_STAGE + PB_AL, ilr, rbase, HH_, 128, tid);
        CP_COMMIT();

        // ================= phase B =================
        float accB[2][3][4];
#pragma unroll
        for (int nf = 0; nf < 2; nf++)
#pragma unroll
            for (int i = 0; i < 3; i++)
#pragma unroll
                for (int q = 0; q < 4; q++) accB[nf][i][q] = 0.f;

#pragma unroll
        for (int kc = 0; kc < 4; kc++) {
            if (kc < 3) { CP_WAIT(1); } else { CP_WAIT(0); }
            __syncthreads();
            bf16* cb = sm + RD + (kc & 1) * PB_STAGE;
#pragma unroll
            for (int ks = 0; ks < 8; ks++) {
                int ko = ks * 16;
                uint32_t ah[4], al[4], bh4[4], bl4[4];
                ldsm4_s(ah, cb + PB_AH, 128, wm * 16, ko, lane);
                ldsm4_s(al, cb + PB_AL, 128, wm * 16, ko, lane);
                ldsm4_n16(bh4, cb + PB_WH, 128, wn * 16, ko, lane);
                ldsm4_n16(bl4, cb + PB_WL, 128, wn * 16, ko, lane);
#pragma unroll
                for (int nf = 0; nf < 2; nf++) {
                    hmma(accB[nf][0], ah, bh4 + 2 * nf);
                    hmma(accB[nf][1], ah, bl4 + 2 * nf);
                    hmma(accB[nf][2], al, bh4 + 2 * nf);
                }
            }
            __syncthreads();
            if (kc < 2) {
                wait_flags(g_fi[grp] + (8 + 4 * kc) * 32, 4, tgtI, lane);
                bf16* ns = sm + RD + (kc & 1) * PB_STAGE;
                int k0 = (kc + 2) * 128;
                ld_sw<32, 16>(ns + PB_AH, ihr, rbase, HH_, k0, tid);
                ld_sw<32, 16>(ns + PB_AL, ilr, rbase, HH_, k0, tid);
                ld_sw<64, 16>(ns + PB_WH, g_w2hTh, (size_t)cbaseB, HH_, k0, tid);
                ld_sw<64, 16>(ns + PB_WL, g_w2hTl, (size_t)cbaseB, HH_, k0, tid);
                CP_COMMIT();
            }
        }

        // ---- epilogue B: compute + h-state stores FIRST, publish, then out --
        float res[2][2][2];
#pragma unroll
        for (int nf = 0; nf < 2; nf++) {
            int cg = cbaseB + wn * 16 + nf * 8 + (lane & 3) * 2;
#pragma unroll
            for (int half = 0; half < 2; half++) {
                bool on = t < ((half == 0) ? len0 : len1);
                size_t rg = (half == 0) ? rg0 : rg1;
                float v0, v1;
                if (on) {
                    float s0 = accB[nf][0][half * 2] + accB[nf][1][half * 2] +
                               accB[nf][2][half * 2];
                    float s1 = accB[nf][0][half * 2 + 1] + accB[nf][1][half * 2 + 1] +
                               accB[nf][2][half * 2 + 1];
                    v0 = fast_tanh(xv[nf][half].x + s0 + pb2[nf][0]);
                    v1 = fast_tanh(xv[nf][half].y + s1 + pb2[nf][1]);
                    h_prev[nf][half * 2] = v0;
                    h_prev[nf][half * 2 + 1] = v1;
                    __nv_bfloat162 hv, lv;
                    hv.x = __float2bfloat16(v0);
                    hv.y = __float2bfloat16(v1);
                    lv.x = __float2bfloat16(v0 - __bfloat162float(hv.x));
                    lv.y = __float2bfloat16(v1 - __bfloat162float(hv.y));
                    *(__nv_bfloat162*)&g_hh[rg * H_ + cg] = hv;
                    *(__nv_bfloat162*)&g_hl[rg * H_ + cg] = lv;
                } else {
                    v0 = h_prev[nf][half * 2];
                    v1 = h_prev[nf][half * 2 + 1];
                }
                res[nf][half][0] = v0;
                res[nf][half][1] = v1;
            }
        }
        __syncthreads();
        if (tid == 0) publish(&g_fh[grp][slot * 32], baseH + (unsigned)t + 2);
        // out writes off the critical path, streaming
#pragma unroll
        for (int nf = 0; nf < 2; nf++) {
            int cg = cbaseB + wn * 16 + nf * 8 + (lane & 3) * 2;
#pragma unroll
            for (int half = 0; half < 2; half++) {
                size_t rg = (half == 0) ? rg0 : rg1;
                __stcs((float2*)&out[(rg * S_ + t) * H_ + cg],
                       make_float2(res[nf][half][0], res[nf][half][1]));
            }
        }
    }
}

// ---------------- launcher --------------------------------------------------
extern "C" void kernel_launch(void* const* d_in, const int* in_sizes, int n_in,
                              void* d_out, int out_size) {
    const float* seq = (const float*)d_in[0];
    const int* lens  = (const int*)d_in[1];
    const float* w1x = (const float*)d_in[2];
    const float* b1x = (const float*)d_in[3];
    const float* w2x = (const float*)d_in[4];
    const float* b2x = (const float*)d_in[5];
    const float* w1h = (const float*)d_in[6];
    const float* b1h = (const float*)d_in[7];
    const float* w2h = (const float*)d_in[8];
    const float* b2h = (const float*)d_in[9];
    float* out = (float*)d_out;

    bf16 *seqh, *seql, *tmph, *tmpl;
    bf16 *w1xh, *w1xl, *w2xh, *w2xl, *w1hh, *w1hl, *w2hh, *w2hl;
    float* xh;
    cudaGetSymbolAddress((void**)&seqh, g_seqh);
    cudaGetSymbolAddress((void**)&seql, g_seql);
    cudaGetSymbolAddress((void**)&tmph, g_tmph);
    cudaGetSymbolAddress((void**)&tmpl, g_tmpl);
    cudaGetSymbolAddress((void**)&xh, g_xh);
    cudaGetSymbolAddress((void**)&w1xh, g_w1xTh);
    cudaGetSymbolAddress((void**)&w1xl, g_w1xTl);
    cudaGetSymbolAddress((void**)&w2xh, g_w2xTh);
    cudaGetSymbolAddress((void**)&w2xl, g_w2xTl);
    cudaGetSymbolAddress((void**)&w1hh, g_w1hTh);
    cudaGetSymbolAddress((void**)&w1hl, g_w1hTl);
    cudaGetSymbolAddress((void**)&w2hh, g_w2hTh);
    cudaGetSymbolAddress((void**)&w2hl, g_w2hTl);

    cudaFuncSetAttribute(ff_mma, cudaFuncAttributeMaxDynamicSharedMemorySize, P1_SMEM);
    cudaFuncSetAttribute(recurrence, cudaFuncAttributeMaxDynamicSharedMemorySize, R_SMEM);

    size_t nseq = (size_t)MTOK * E_;
    split_kernel<<<(unsigned)((nseq + 255) / 256), 256>>>(seq, seqh, seql, nseq);
    transpose_split<<<(E_ * HH_ + 255) / 256, 256>>>(w1x, w1xh, w1xl, E_, HH_);
    transpose_split<<<(HH_ * H_ + 255) / 256, 256>>>(w2x, w2xh, w2xl, HH_, H_);
    transpose_split<<<(H_ * HH_ + 255) / 256, 256>>>(w1h, w1hh, w1hl, H_, HH_);
    transpose_split<<<(HH_ * H_ + 255) / 256, 256>>>(w2h, w2hh, w2hl, HH_, H_);

    ff_mma<<<dim3(HH_ / 128, MTOK / 128), 256, P1_SMEM>>>(
        seqh, seql, w1xh, w1xl, b1x, nullptr, tmph, tmpl, E_, HH_, 1);
    ff_mma<<<dim3(H_ / 128, MTOK / 128), 256, P1_SMEM>>>(
        tmph, tmpl, w2xh, w2xl, b2x, xh, nullptr, nullptr, HH_, H_, 0);

    recurrence<<<128, 256, R_SMEM>>>(b1h, b2h, lens, out);
}

// round 15
// speedup vs baseline: 1.0912x; 1.0100x over previous
#include <cuda_runtime.h>
#include <cuda_bf16.h>
#include <cstdint>

#define B_ 256
#define S_ 512
#define E_ 512
#define H_ 1024
#define HH_ 512
#define MTOK (B_ * S_)

typedef __nv_bfloat16 bf16;

// ---------------- device-global scratch ------------------------------------
__device__ bf16 g_seqh[(size_t)MTOK * E_];
__device__ bf16 g_seql[(size_t)MTOK * E_];
__device__ bf16 g_tmph[(size_t)MTOK * HH_];
__device__ bf16 g_tmpl[(size_t)MTOK * HH_];
__device__ float g_xh[(size_t)MTOK * H_];
__device__ bf16 g_w1xTh[HH_ * E_], g_w1xTl[HH_ * E_];   // [N,K]
__device__ bf16 g_w2xTh[H_ * HH_], g_w2xTl[H_ * HH_];
__device__ bf16 g_w1hTh[HH_ * H_], g_w1hTl[HH_ * H_];
__device__ bf16 g_w2hTh[H_ * HH_], g_w2hTl[H_ * HH_];
__device__ bf16 g_hh[B_ * H_], g_hl[B_ * H_];
__device__ bf16 g_ih[2][B_ * HH_], g_il[2][B_ * HH_];   // inter double-buffered
// monotonic per-CTA flags (128B stride per flag)
__device__ volatile unsigned g_fh[8][16 * 32];
__device__ volatile unsigned g_fi[8][16 * 32];

// ---------------- helpers ----------------------------------------------------
__device__ __forceinline__ uint32_t smem_u32(const void* p) {
    uint32_t r;
    asm("{ .reg .u64 t; cvta.to.shared.u64 t, %1; cvt.u32.u64 %0, t; }" : "=r"(r) : "l"(p));
    return r;
}
__device__ __forceinline__ float fast_tanh(float x) {
    float y; asm("tanh.approx.f32 %0, %1;" : "=f"(y) : "f"(x)); return y;
}
__device__ __forceinline__ void hmma(float c[4], const uint32_t a[4], const uint32_t b[2]) {
    asm volatile("mma.sync.aligned.m16n8k16.row.col.f32.bf16.bf16.f32 "
        "{%0,%1,%2,%3}, {%4,%5,%6,%7}, {%8,%9}, {%0,%1,%2,%3};"
        : "+f"(c[0]), "+f"(c[1]), "+f"(c[2]), "+f"(c[3])
        : "r"(a[0]), "r"(a[1]), "r"(a[2]), "r"(a[3]), "r"(b[0]), "r"(b[1]));
}
// swizzled ldmatrix x4: A frag m16k16
__device__ __forceinline__ void ldsm4_s(uint32_t a[4], const bf16* tb, int rowlen,
                                        int rowbase, int ko, int lane) {
    int row = rowbase + (lane & 15);
    int seg = (ko >> 3) + (lane >> 4);
    uint32_t addr = smem_u32(tb + row * rowlen + ((seg ^ (row & 7)) << 3));
    asm volatile("ldmatrix.sync.aligned.m8n8.x4.shared.b16 {%0,%1,%2,%3}, [%4];"
        : "=r"(a[0]), "=r"(a[1]), "=r"(a[2]), "=r"(a[3]) : "r"(addr));
}
// fused x4: B frags for TWO adjacent n8 blocks (n16): b[0..1]=nf0, b[2..3]=nf1
__device__ __forceinline__ void ldsm4_n16(uint32_t b[4], const bf16* tb, int rowlen,
                                          int rowbase, int ko, int lane) {
    int row = rowbase + ((lane >> 4) << 3) + (lane & 7);
    int seg = (ko >> 3) + ((lane >> 3) & 1);
    uint32_t addr = smem_u32(tb + row * rowlen + ((seg ^ (row & 7)) << 3));
    asm volatile("ldmatrix.sync.aligned.m8n8.x4.shared.b16 {%0,%1,%2,%3}, [%4];"
        : "=r"(b[0]), "=r"(b[1]), "=r"(b[2]), "=r"(b[3]) : "r"(addr));
}
__device__ __forceinline__ void ldsm2_s(uint32_t b[2], const bf16* tb, int rowlen,
                                        int rowbase, int ko, int lane) {
    int row = rowbase + (lane & 7);
    int seg = (ko >> 3) + ((lane >> 3) & 1);
    uint32_t addr = smem_u32(tb + row * rowlen + ((seg ^ (row & 7)) << 3));
    asm volatile("ldmatrix.sync.aligned.m8n8.x2.shared.b16 {%0,%1}, [%2];"
        : "=r"(b[0]), "=r"(b[1]) : "r"(addr));
}
__device__ __forceinline__ void cp16(bf16* s, const bf16* g) {
    uint32_t sa = smem_u32(s);
    asm volatile("cp.async.cg.shared.global [%0], [%1], 16;" :: "r"(sa), "l"(g));
}
#define CP_COMMIT() asm volatile("cp.async.commit_group;" ::: "memory")
#define CP_WAIT(n) asm volatile("cp.async.wait_group %0;" :: "n"(n) : "memory")

// async-load [ROWS x SEGS*8] bf16 tile, swizzled
template <int ROWS, int SEGS>
__device__ __forceinline__ void ld_sw(bf16* dst, const bf16* __restrict__ src,
                                      size_t row0, int ld, int k0, int tid) {
#pragma unroll
    for (int i = tid; i < ROWS * SEGS; i += 256) {
        int r = i / SEGS, c = i % SEGS;
        cp16(dst + r * SEGS * 8 + ((c ^ (r & 7)) << 3),
             src + (row0 + (size_t)r) * (size_t)ld + k0 + c * 8);
    }
}

// warp-parallel acquire poll on cnt flags (cnt power of 2); all threads call
__device__ __forceinline__ void wait_flags(volatile unsigned* fl, int cnt,
                                           unsigned tgt, int lane) {
    const unsigned* p = (const unsigned*)(fl + (lane & (cnt - 1)) * 32);
    unsigned v;
    do {
        asm volatile("ld.acquire.gpu.u32 %0, [%1];" : "=r"(v) : "l"(p) : "memory");
    } while (__any_sync(0xffffffffu, (int)(v - tgt) < 0));
}
__device__ __forceinline__ void publish(volatile unsigned* fl, unsigned val) {
    __threadfence();
    asm volatile("st.release.gpu.u32 [%0], %1;" :: "l"((unsigned*)fl), "r"(val) : "memory");
}

// ---------------- prep kernels ----------------------------------------------
__global__ void split_kernel(const float* __restrict__ x, bf16* __restrict__ h,
                             bf16* __restrict__ l, size_t n) {
    size_t i = (size_t)blockIdx.x * 256 + threadIdx.x;
    if (i < n) {
        float v = x[i];
        bf16 a = __float2bfloat16(v);
        h[i] = a;
        l[i] = __float2bfloat16(v - __bfloat162float(a));
    }
}
__global__ void transpose_split(const float* __restrict__ W, bf16* __restrict__ Th,
                                bf16* __restrict__ Tl, int K, int N) {
    int idx = blockIdx.x * 256 + threadIdx.x;
    if (idx < N * K) {
        int n = idx / K, k = idx % K;
        float v = W[k * N + n];
        bf16 a = __float2bfloat16(v);
        Th[idx] = a;
        Tl[idx] = __float2bfloat16(v - __bfloat162float(a));
    }
}

// ---------------- phase-1 GEMM: out = act(A @ W^T + bias) -------------------
// 3-stage single-sync cp.async pipeline. Tile 128x128, K-chunk 64.
#define P1_AH 0
#define P1_AL 8192
#define P1_BH 16384
#define P1_BL 24576
#define P1_BUF 32768
#define P1_SMEM (3 * P1_BUF * 2)

__global__ __launch_bounds__(256) void ff_mma(
    const bf16* __restrict__ Ah, const bf16* __restrict__ Al,
    const bf16* __restrict__ Bh, const bf16* __restrict__ Bl,
    const float* __restrict__ bias, float* __restrict__ outF,
    bf16* __restrict__ outH, bf16* __restrict__ outL,
    int K, int N, int relu_split)
{
    extern __shared__ bf16 sm[];
    const int tid = threadIdx.x, lane = tid & 31, wid = tid >> 5;
    const int wm = wid & 3, wn = wid >> 2;
    const size_t rowBase = (size_t)blockIdx.y * 128;
    const int colBase = blockIdx.x * 128;
    const int nch = K / 64;

    float acc[2][8][4];
#pragma unroll
    for (int i = 0; i < 2; i++)
#pragma unroll
        for (int j = 0; j < 8; j++)
#pragma unroll
            for (int q = 0; q < 4; q++) acc[i][j][q] = 0.f;

    // prologue: fill 2 of 3 stages
#pragma unroll
    for (int p = 0; p < 2; p++) {
        bf16* nb = sm + p * P1_BUF;
        int k0 = p * 64;
        ld_sw<128, 8>(nb + P1_AH, Ah, rowBase, K, k0, tid);
        ld_sw<128, 8>(nb + P1_AL, Al, rowBase, K, k0, tid);
        ld_sw<128, 8>(nb + P1_BH, Bh, (size_t)colBase, K, k0, tid);
        ld_sw<128, 8>(nb + P1_BL, Bl, (size_t)colBase, K, k0, tid);
        CP_COMMIT();
    }

    for (int kc = 0; kc < nch; kc++) {
        if (kc < nch - 1) { CP_WAIT(1); } else { CP_WAIT(0); }
        __syncthreads();
        if (kc + 2 < nch) {   // issue into stage freed last iteration
            bf16* nb = sm + ((kc + 2) % 3) * P1_BUF;
            int k0 = (kc + 2) * 64;
            ld_sw<128, 8>(nb + P1_AH, Ah, rowBase, K, k0, tid);
            ld_sw<128, 8>(nb + P1_AL, Al, rowBase, K, k0, tid);
            ld_sw<128, 8>(nb + P1_BH, Bh, (size_t)colBase, K, k0, tid);
            ld_sw<128, 8>(nb + P1_BL, Bl, (size_t)colBase, K, k0, tid);
            CP_COMMIT();
        }
        bf16* cb = sm + (kc % 3) * P1_BUF;
#pragma unroll
        for (int ks = 0; ks < 4; ks++) {
            int ko = ks * 16;
            uint32_t ah[2][4], al[2][4];
#pragma unroll
            for (int mf = 0; mf < 2; mf++) {
                ldsm4_s(ah[mf], cb + P1_AH, 64, wm * 32 + mf * 16, ko, lane);
                ldsm4_s(al[mf], cb + P1_AL, 64, wm * 32 + mf * 16, ko, lane);
            }
#pragma unroll
            for (int np = 0; np < 4; np++) {
                uint32_t bh4[4], bl4[4];
                ldsm4_n16(bh4, cb + P1_BH, 64, wn * 64 + np * 16, ko, lane);
                ldsm4_n16(bl4, cb + P1_BL, 64, wn * 64 + np * 16, ko, lane);
#pragma unroll
                for (int s = 0; s < 2; s++) {
#pragma unroll
                    for (int mf = 0; mf < 2; mf++) {
                        hmma(acc[mf][np * 2 + s], ah[mf], bh4 + 2 * s);
                        hmma(acc[mf][np * 2 + s], ah[mf], bl4 + 2 * s);
                        hmma(acc[mf][np * 2 + s], al[mf], bh4 + 2 * s);
                    }
                }
            }
        }
    }

#pragma unroll
    for (int mf = 0; mf < 2; mf++) {
#pragma unroll
        for (int nf = 0; nf < 8; nf++) {
            int cg = colBase + wn * 64 + nf * 8 + (lane & 3) * 2;
            float b0 = bias[cg], b1 = bias[cg + 1];
#pragma unroll
            for (int half = 0; half < 2; half++) {
                size_t rg = rowBase + wm * 32 + mf * 16 + (lane >> 2) + half * 8;
                float v0 = acc[mf][nf][half * 2] + b0;
                float v1 = acc[mf][nf][half * 2 + 1] + b1;
                if (relu_split) {
                    v0 = fmaxf(v0, 0.f);
                    v1 = fmaxf(v1, 0.f);
                    __nv_bfloat162 hv, lv;
                    hv.x = __float2bfloat16(v0);
                    hv.y = __float2bfloat16(v1);
                    lv.x = __float2bfloat16(v0 - __bfloat162float(hv.x));
                    lv.y = __float2bfloat16(v1 - __bfloat162float(hv.y));
                    *(__nv_bfloat162*)&outH[rg * N + cg] = hv;
                    *(__nv_bfloat162*)&outL[rg * N + cg] = lv;
                } else {
                    *(float2*)&outF[rg * N + cg] = make_float2(v0, v1);
                }
            }
        }
    }
}

// ---------------- persistent recurrence: 8 groups x 16 CTAs -----------------
// R14 structure; change: inter-flag waits split per chunk producer set.
#define RW_H 0
#define RW_L 32768
#define RD 65536
#define PB_AH 0
#define PB_AL 4096
#define PB_WH 8192
#define PB_WL 16384
#define PB_STAGE 24576
#define PA_ST 16384
#define R_SMEM ((65536 + 2 * 24576) * 2)

__global__ __launch_bounds__(256) void recurrence(
    const float* __restrict__ b1h, const float* __restrict__ b2h,
    const int* __restrict__ lens, float* __restrict__ out)
{
    extern __shared__ bf16 sm[];
    bf16* smWH = sm + RW_H;
    bf16* smWL = sm + RW_L;
    const int tid = threadIdx.x, lane = tid & 31, wid = tid >> 5;
    const int wm = wid & 1, wn = wid >> 1;  // 2m x 4n warps
    const int cta = blockIdx.x;
    const int grp = cta >> 4;
    const int slot = cta & 15;
    const size_t rbase = (size_t)grp * 32;
    const int cbaseA = slot * 32;
    const int cbaseB = slot * 64;

    const unsigned baseH = g_fh[grp][slot * 32];
    const unsigned baseI = g_fi[grp][slot * 32];

    // zero h state by COLUMN ownership
    for (int i = tid; i < 32 * 32; i += 256) {
        int r = i >> 5, c = (i & 31) * 2;
        size_t j = (rbase + r) * H_ + cbaseB + c;
        *(__nv_bfloat162*)&g_hh[j] = __nv_bfloat162{__float2bfloat16(0.f), __float2bfloat16(0.f)};
        *(__nv_bfloat162*)&g_hl[j] = __nv_bfloat162{__float2bfloat16(0.f), __float2bfloat16(0.f)};
    }
    __syncthreads();
    if (tid == 0) publish(&g_fh[grp][slot * 32], baseH + 1);

    // resident phase-A weights
    for (int i = tid; i < 32 * 128; i += 256) {
        int r = i >> 7, c = i & 127;
        int d = r * 1024 + ((c ^ (r & 7)) << 3);
        *(uint4*)(smWH + d) = *(const uint4*)&g_w1hTh[(size_t)(cbaseA + r) * H_ + c * 8];
        *(uint4*)(smWL + d) = *(const uint4*)&g_w1hTl[(size_t)(cbaseA + r) * H_ + c * 8];
    }
    __syncthreads();

    const size_t rg0 = rbase + wm * 16 + (lane >> 2);
    const size_t rg1 = rg0 + 8;
    const int len0 = lens[rg0], len1 = lens[rg1];
    const int cgA = cbaseA + wn * 8 + (lane & 3) * 2;
    const float pb1_0 = b1h[cgA], pb1_1 = b1h[cgA + 1];
    float pb2[2][2];
#pragma unroll
    for (int nf = 0; nf < 2; nf++) {
        int cg = cbaseB + wn * 16 + nf * 8 + (lane & 3) * 2;
        pb2[nf][0] = b2h[cg];
        pb2[nf][1] = b2h[cg + 1];
    }
    float h_prev[2][4];
#pragma unroll
    for (int nf = 0; nf < 2; nf++)
#pragma unroll
        for (int q = 0; q < 4; q++) h_prev[nf][q] = 0.f;

    for (int t = 0; t < S_; t++) {
        const unsigned tgtH = baseH + (unsigned)t + 1;
        const unsigned tgtI = baseI + (unsigned)t + 1;
        const int par = t & 1;
        const bf16* ihr = g_ih[par];
        const bf16* ilr = g_il[par];

        // xh prefetch (flag-independent)
        float2 xv[2][2];
#pragma unroll
        for (int nf = 0; nf < 2; nf++) {
            int cg = cbaseB + wn * 16 + nf * 8 + (lane & 3) * 2;
            xv[nf][0] = *(const float2*)&g_xh[(rg0 * S_ + t) * H_ + cg];
            xv[nf][1] = *(const float2*)&g_xh[(rg1 * S_ + t) * H_ + cg];
        }

        // ---- phase A prologue: fill 2 of 3 stages (K-chunks of 256) ----
#pragma unroll
        for (int p = 0; p < 2; p++) {
            wait_flags(g_fh[grp] + 4 * p * 32, 4, tgtH, lane);
            bf16* hs = sm + RD + p * PA_ST;
            ld_sw<32, 32>(hs, g_hh, rbase, H_, p * 256, tid);
            ld_sw<32, 32>(hs + 8192, g_hl, rbase, H_, p * 256, tid);
            CP_COMMIT();
        }

        // ================= phase A (4 chunks of K=256, ONE sync each) ======
        float accA[3][4];
#pragma unroll
        for (int i = 0; i < 3; i++)
#pragma unroll
            for (int q = 0; q < 4; q++) accA[i][q] = 0.f;

#pragma unroll
        for (int kc = 0; kc < 4; kc++) {
            if (kc < 3) { CP_WAIT(1); } else { CP_WAIT(0); }
            __syncthreads();
            if (kc < 2) {   // issue chunk kc+2 into stage freed last iteration
                int c = kc + 2;
                wait_flags(g_fh[grp] + 4 * c * 32, 4, tgtH, lane);
                bf16* ns = sm + RD + (c % 3) * PA_ST;
                ld_sw<32, 32>(ns, g_hh, rbase, H_, c * 256, tid);
                ld_sw<32, 32>(ns + 8192, g_hl, rbase, H_, c * 256, tid);
                CP_COMMIT();
            }
            bf16* hs = sm + RD + (kc % 3) * PA_ST;
#pragma unroll
            for (int ks = 0; ks < 16; ks++) {
                int ko = ks * 16;
                uint32_t ah[4], al[4], bh[2], bl[2];
                ldsm4_s(ah, hs, 256, wm * 16, ko, lane);
                ldsm4_s(al, hs + 8192, 256, wm * 16, ko, lane);
                ldsm2_s(bh, smWH, 1024, wn * 8, kc * 256 + ko, lane);
                ldsm2_s(bl, smWL, 1024, wn * 8, kc * 256 + ko, lane);
                hmma(accA[0], ah, bh);
                hmma(accA[1], ah, bl);
                hmma(accA[2], al, bh);
            }
        }

        // ---- epilogue A: relu + split -> inter (buffer t&1) ----
#pragma unroll
        for (int half = 0; half < 2; half++) {
            size_t rg = (half == 0) ? rg0 : rg1;
            float v0 = fmaxf(accA[0][half * 2] + accA[1][half * 2] +
                             accA[2][half * 2] + pb1_0, 0.f);
            float v1 = fmaxf(accA[0][half * 2 + 1] + accA[1][half * 2 + 1] +
                             accA[2][half * 2 + 1] + pb1_1, 0.f);
            __nv_bfloat162 hv, lv;
            hv.x = __float2bfloat16(v0);
            hv.y = __float2bfloat16(v1);
            lv.x = __float2bfloat16(v0 - __bfloat162float(hv.x));
            lv.y = __float2bfloat16(v1 - __bfloat162float(hv.y));
            *(__nv_bfloat162*)&g_ih[par][rg * HH_ + cgA] = hv;
            *(__nv_bfloat162*)&g_il[par][rg * HH_ + cgA] = lv;
        }
        __syncthreads();   // all warps done with PA stages + inter stores done
        if (tid == 0) publish(&g_fi[grp][slot * 32], tgtI);

        // W2 prefetch chunks 0,1 (flag-independent)
        ld_sw<64, 16>(sm + RD + PB_WH, g_w2hTh, (size_t)cbaseB, HH_, 0, tid);
        ld_sw<64, 16>(sm + RD + PB_WL, g_w2hTl, (size_t)cbaseB, HH_, 0, tid);
        CP_COMMIT();
        ld_sw<64, 16>(sm + RD + PB_STAGE + PB_WH, g_w2hTh, (size_t)cbaseB, HH_, 128, tid);
        ld_sw<64, 16>(sm + RD + PB_STAGE + PB_WL, g_w2hTl, (size_t)cbaseB, HH_, 128, tid);
        CP_COMMIT();

        // inter chunks 0,1: wait only each chunk's producers (4 CTAs each)
        wait_flags(g_fi[grp], 4, tgtI, lane);
        ld_sw<32, 16>(sm + RD + PB_AH, ihr, rbase, HH_, 0, tid);
        ld_sw<32, 16>(sm + RD + PB_AL, ilr, rbase, HH_, 0, tid);
        CP_COMMIT();
        wait_flags(g_fi[grp] + 4 * 32, 4, tgtI, lane);
        ld_sw<32, 16>(sm + RD + PB_STAGE + PB_AH, ihr, rbase, HH_, 128, tid);
        ld_sw<32, 16>(sm + RD + PB_STAGE + PB_AL, ilr, rbase, HH_, 128, tid);
        CP_COMMIT();

        // ================= phase B =================
        float accB[2][3][4];
#pragma unroll
        for (int nf = 0; nf < 2; nf++)
#pragma unroll
            for (int i = 0; i < 3; i++)
#pragma unroll
                for (int q = 0; q < 4; q++) accB[nf][i][q] = 0.f;

#pragma unroll
        for (int kc = 0; kc < 4; kc++) {
            if (kc < 3) { CP_WAIT(1); } else { CP_WAIT(0); }
            __syncthreads();
            bf16* cb = sm + RD + (kc & 1) * PB_STAGE;
#pragma unroll
            for (int ks = 0; ks < 8; ks++) {
                int ko = ks * 16;
                uint32_t ah[4], al[4], bh4[4], bl4[4];
                ldsm4_s(ah, cb + PB_AH, 128, wm * 16, ko, lane);
                ldsm4_s(al, cb + PB_AL, 128, wm * 16, ko, lane);
                ldsm4_n16(bh4, cb + PB_WH, 128, wn * 16, ko, lane);
                ldsm4_n16(bl4, cb + PB_WL, 128, wn * 16, ko, lane);
#pragma unroll
                for (int nf = 0; nf < 2; nf++) {
                    hmma(accB[nf][0], ah, bh4 + 2 * nf);
                    hmma(accB[nf][1], ah, bl4 + 2 * nf);
                    hmma(accB[nf][2], al, bh4 + 2 * nf);
                }
            }
            __syncthreads();
            if (kc < 2) {
                wait_flags(g_fi[grp] + (8 + 4 * kc) * 32, 4, tgtI, lane);
                bf16* ns = sm + RD + (kc & 1) * PB_STAGE;
                int k0 = (kc + 2) * 128;
                ld_sw<32, 16>(ns + PB_AH, ihr, rbase, HH_, k0, tid);
                ld_sw<32, 16>(ns + PB_AL, ilr, rbase, HH_, k0, tid);
                ld_sw<64, 16>(ns + PB_WH, g_w2hTh, (size_t)cbaseB, HH_, k0, tid);
                ld_sw<64, 16>(ns + PB_WL, g_w2hTl, (size_t)cbaseB, HH_, k0, tid);
                CP_COMMIT();
            }
        }

        // ---- epilogue B: compute + h-state stores FIRST, publish, then out --
        float res[2][2][2];
#pragma unroll
        for (int nf = 0; nf < 2; nf++) {
            int cg = cbaseB + wn * 16 + nf * 8 + (lane & 3) * 2;
#pragma unroll
            for (int half = 0; half < 2; half++) {
                bool on = t < ((half == 0) ? len0 : len1);
                size_t rg = (half == 0) ? rg0 : rg1;
                float v0, v1;
                if (on) {
                    float s0 = accB[nf][0][half * 2] + accB[nf][1][half * 2] +
                               accB[nf][2][half * 2];
                    float s1 = accB[nf][0][half * 2 + 1] + accB[nf][1][half * 2 + 1] +
                               accB[nf][2][half * 2 + 1];
                    v0 = fast_tanh(xv[nf][half].x + s0 + pb2[nf][0]);
                    v1 = fast_tanh(xv[nf][half].y + s1 + pb2[nf][1]);
                    h_prev[nf][half * 2] = v0;
                    h_prev[nf][half * 2 + 1] = v1;
                    __nv_bfloat162 hv, lv;
                    hv.x = __float2bfloat16(v0);
                    hv.y = __float2bfloat16(v1);
                    lv.x = __float2bfloat16(v0 - __bfloat162float(hv.x));
                    lv.y = __float2bfloat16(v1 - __bfloat162float(hv.y));
                    *(__nv_bfloat162*)&g_hh[rg * H_ + cg] = hv;
                    *(__nv_bfloat162*)&g_hl[rg * H_ + cg] = lv;
                } else {
                    v0 = h_prev[nf][half * 2];
                    v1 = h_prev[nf][half * 2 + 1];
                }
                res[nf][half][0] = v0;
                res[nf][half][1] = v1;
            }
        }
        __syncthreads();
        if (tid == 0) publish(&g_fh[grp][slot * 32], baseH + (unsigned)t + 2);
        // out writes off the critical path, streaming
#pragma unroll
        for (int nf = 0; nf < 2; nf++) {
            int cg = cbaseB + wn * 16 + nf * 8 + (lane & 3) * 2;
#pragma unroll
            for (int half = 0; half < 2; half++) {
                size_t rg = (half == 0) ? rg0 : rg1;
                __stcs((float2*)&out[(rg * S_ + t) * H_ + cg],
                       make_float2(res[nf][half][0], res[nf][half][1]));
            }
        }
    }
}

// ---------------- launcher --------------------------------------------------
extern "C" void kernel_launch(void* const* d_in, const int* in_sizes, int n_in,
                              void* d_out, int out_size) {
    const float* seq = (const float*)d_in[0];
    const int* lens  = (const int*)d_in[1];
    const float* w1x = (const float*)d_in[2];
    const float* b1x = (const float*)d_in[3];
    const float* w2x = (const float*)d_in[4];
    const float* b2x = (const float*)d_in[5];
    const float* w1h = (const float*)d_in[6];
    const float* b1h = (const float*)d_in[7];
    const float* w2h = (const float*)d_in[8];
    const float* b2h = (const float*)d_in[9];
    float* out = (float*)d_out;

    bf16 *seqh, *seql, *tmph, *tmpl;
    bf16 *w1xh, *w1xl, *w2xh, *w2xl, *w1hh, *w1hl, *w2hh, *w2hl;
    float* xh;
    cudaGetSymbolAddress((void**)&seqh, g_seqh);
    cudaGetSymbolAddress((void**)&seql, g_seql);
    cudaGetSymbolAddress((void**)&tmph, g_tmph);
    cudaGetSymbolAddress((void**)&tmpl, g_tmpl);
    cudaGetSymbolAddress((void**)&xh, g_xh);
    cudaGetSymbolAddress((void**)&w1xh, g_w1xTh);
    cudaGetSymbolAddress((void**)&w1xl, g_w1xTl);
    cudaGetSymbolAddress((void**)&w2xh, g_w2xTh);
    cudaGetSymbolAddress((void**)&w2xl, g_w2xTl);
    cudaGetSymbolAddress((void**)&w1hh, g_w1hTh);
    cudaGetSymbolAddress((void**)&w1hl, g_w1hTl);
    cudaGetSymbolAddress((void**)&w2hh, g_w2hTh);
    cudaGetSymbolAddress((void**)&w2hl, g_w2hTl);

    cudaFuncSetAttribute(ff_mma, cudaFuncAttributeMaxDynamicSharedMemorySize, P1_SMEM);
    cudaFuncSetAttribute(recurrence, cudaFuncAttributeMaxDynamicSharedMemorySize, R_SMEM);

    size_t nseq = (size_t)MTOK * E_;
    split_kernel<<<(unsigned)((nseq + 255) / 256), 256>>>(seq, seqh, seql, nseq);
    transpose_split<<<(E_ * HH_ + 255) / 256, 256>>>(w1x, w1xh, w1xl, E_, HH_);
    transpose_split<<<(HH_ * H_ + 255) / 256, 256>>>(w2x, w2xh, w2xl, HH_, H_);
    transpose_split<<<(H_ * HH_ + 255) / 256, 256>>>(w1h, w1hh, w1hl, H_, HH_);
    transpose_split<<<(HH_ * H_ + 255) / 256, 256>>>(w2h, w2hh, w2hl, HH_, H_);

    ff_mma<<<dim3(HH_ / 128, MTOK / 128), 256, P1_SMEM>>>(
        seqh, seql, w1xh, w1xl, b1x, nullptr, tmph, tmpl, E_, HH_, 1);
    ff_mma<<<dim3(H_ / 128, MTOK / 128), 256, P1_SMEM>>>(
        tmph, tmpl, w2xh, w2xl, b2x, xh, nullptr, nullptr, HH_, H_, 0);

    recurrence<<<128, 256, R_SMEM>>>(b1h, b2h, lens, out);
}

// round 16
// speedup vs baseline: 1.1029x; 1.0107x over previous
#include <cuda_runtime.h>
#include <cuda_bf16.h>
#include <cstdint>

#define B_ 256
#define S_ 512
#define E_ 512
#define H_ 1024
#define HH_ 512
#define MTOK (B_ * S_)

typedef __nv_bfloat16 bf16;

// ---------------- device-global scratch ------------------------------------
__device__ bf16 g_seqh[(size_t)MTOK * E_];
__device__ bf16 g_seql[(size_t)MTOK * E_];
__device__ bf16 g_tmph[(size_t)MTOK * HH_];
__device__ bf16 g_tmpl[(size_t)MTOK * HH_];
__device__ float g_xh[(size_t)MTOK * H_];
__device__ bf16 g_w1xTh[HH_ * E_], g_w1xTl[HH_ * E_];   // [N,K]
__device__ bf16 g_w2xTh[H_ * HH_], g_w2xTl[H_ * HH_];
__device__ bf16 g_w1hTh[HH_ * H_], g_w1hTl[HH_ * H_];
__device__ bf16 g_w2hTh[H_ * HH_], g_w2hTl[H_ * HH_];
__device__ bf16 g_hh[B_ * H_], g_hl[B_ * H_];
__device__ bf16 g_ih[2][B_ * HH_], g_il[2][B_ * HH_];   // inter double-buffered
// monotonic per-CTA flags (128B stride per flag)
__device__ volatile unsigned g_fh[8][16 * 32];
__device__ volatile unsigned g_fi[8][16 * 32];

// ---------------- helpers ----------------------------------------------------
__device__ __forceinline__ uint32_t smem_u32(const void* p) {
    uint32_t r;
    asm("{ .reg .u64 t; cvta.to.shared.u64 t, %1; cvt.u32.u64 %0, t; }" : "=r"(r) : "l"(p));
    return r;
}
__device__ __forceinline__ float fast_tanh(float x) {
    float y; asm("tanh.approx.f32 %0, %1;" : "=f"(y) : "f"(x)); return y;
}
__device__ __forceinline__ void hmma(float c[4], const uint32_t a[4], const uint32_t b[2]) {
    asm volatile("mma.sync.aligned.m16n8k16.row.col.f32.bf16.bf16.f32 "
        "{%0,%1,%2,%3}, {%4,%5,%6,%7}, {%8,%9}, {%0,%1,%2,%3};"
        : "+f"(c[0]), "+f"(c[1]), "+f"(c[2]), "+f"(c[3])
        : "r"(a[0]), "r"(a[1]), "r"(a[2]), "r"(a[3]), "r"(b[0]), "r"(b[1]));
}
// swizzled ldmatrix x4: A frag m16k16
__device__ __forceinline__ void ldsm4_s(uint32_t a[4], const bf16* tb, int rowlen,
                                        int rowbase, int ko, int lane) {
    int row = rowbase + (lane & 15);
    int seg = (ko >> 3) + (lane >> 4);
    uint32_t addr = smem_u32(tb + row * rowlen + ((seg ^ (row & 7)) << 3));
    asm volatile("ldmatrix.sync.aligned.m8n8.x4.shared.b16 {%0,%1,%2,%3}, [%4];"
        : "=r"(a[0]), "=r"(a[1]), "=r"(a[2]), "=r"(a[3]) : "r"(addr));
}
// fused x4: B frags for TWO adjacent n8 blocks (n16): b[0..1]=nf0, b[2..3]=nf1
__device__ __forceinline__ void ldsm4_n16(uint32_t b[4], const bf16* tb, int rowlen,
                                          int rowbase, int ko, int lane) {
    int row = rowbase + ((lane >> 4) << 3) + (lane & 7);
    int seg = (ko >> 3) + ((lane >> 3) & 1);
    uint32_t addr = smem_u32(tb + row * rowlen + ((seg ^ (row & 7)) << 3));
    asm volatile("ldmatrix.sync.aligned.m8n8.x4.shared.b16 {%0,%1,%2,%3}, [%4];"
        : "=r"(b[0]), "=r"(b[1]), "=r"(b[2]), "=r"(b[3]) : "r"(addr));
}
__device__ __forceinline__ void ldsm2_s(uint32_t b[2], const bf16* tb, int rowlen,
                                        int rowbase, int ko, int lane) {
    int row = rowbase + (lane & 7);
    int seg = (ko >> 3) + ((lane >> 3) & 1);
    uint32_t addr = smem_u32(tb + row * rowlen + ((seg ^ (row & 7)) << 3));
    asm volatile("ldmatrix.sync.aligned.m8n8.x2.shared.b16 {%0,%1}, [%2];"
        : "=r"(b[0]), "=r"(b[1]) : "r"(addr));
}
__device__ __forceinline__ void cp16(bf16* s, const bf16* g) {
    uint32_t sa = smem_u32(s);
    asm volatile("cp.async.cg.shared.global [%0], [%1], 16;" :: "r"(sa), "l"(g));
}
#define CP_COMMIT() asm volatile("cp.async.commit_group;" ::: "memory")
#define CP_WAIT(n) asm volatile("cp.async.wait_group %0;" :: "n"(n) : "memory")

// async-load [ROWS x SEGS*8] bf16 tile, swizzled
template <int ROWS, int SEGS>
__device__ __forceinline__ void ld_sw(bf16* dst, const bf16* __restrict__ src,
                                      size_t row0, int ld, int k0, int tid) {
#pragma unroll
    for (int i = tid; i < ROWS * SEGS; i += 256) {
        int r = i / SEGS, c = i % SEGS;
        cp16(dst + r * SEGS * 8 + ((c ^ (r & 7)) << 3),
             src + (row0 + (size_t)r) * (size_t)ld + k0 + c * 8);
    }
}

// warp-parallel acquire poll on cnt flags (cnt power of 2); all threads call
__device__ __forceinline__ void wait_flags(volatile unsigned* fl, int cnt,
                                           unsigned tgt, int lane) {
    const unsigned* p = (const unsigned*)(fl + (lane & (cnt - 1)) * 32);
    unsigned v;
    do {
        asm volatile("ld.acquire.gpu.u32 %0, [%1];" : "=r"(v) : "l"(p) : "memory");
    } while (__any_sync(0xffffffffu, (int)(v - tgt) < 0));
}
__device__ __forceinline__ void publish(volatile unsigned* fl, unsigned val) {
    __threadfence();
    asm volatile("st.release.gpu.u32 [%0], %1;" :: "l"((unsigned*)fl), "r"(val) : "memory");
}

// ---------------- prep kernels ----------------------------------------------
__global__ void split_kernel(const float* __restrict__ x, bf16* __restrict__ h,
                             bf16* __restrict__ l, size_t n) {
    size_t i = (size_t)blockIdx.x * 256 + threadIdx.x;
    if (i < n) {
        float v = x[i];
        bf16 a = __float2bfloat16(v);
        h[i] = a;
        l[i] = __float2bfloat16(v - __bfloat162float(a));
    }
}
__global__ void transpose_split(const float* __restrict__ W, bf16* __restrict__ Th,
                                bf16* __restrict__ Tl, int K, int N) {
    int idx = blockIdx.x * 256 + threadIdx.x;
    if (idx < N * K) {
        int n = idx / K, k = idx % K;
        float v = W[k * N + n];
        bf16 a = __float2bfloat16(v);
        Th[idx] = a;
        Tl[idx] = __float2bfloat16(v - __bfloat162float(a));
    }
}

// ---------------- phase-1 GEMM: out = act(A @ W^T + bias) -------------------
// 3-stage single-sync cp.async pipeline. Tile 128x128, K-chunk 64.
#define P1_AH 0
#define P1_AL 8192
#define P1_BH 16384
#define P1_BL 24576
#define P1_BUF 32768
#define P1_SMEM (3 * P1_BUF * 2)

__global__ __launch_bounds__(256) void ff_mma(
    const bf16* __restrict__ Ah, const bf16* __restrict__ Al,
    const bf16* __restrict__ Bh, const bf16* __restrict__ Bl,
    const float* __restrict__ bias, float* __restrict__ outF,
    bf16* __restrict__ outH, bf16* __restrict__ outL,
    int K, int N, int relu_split)
{
    extern __shared__ bf16 sm[];
    const int tid = threadIdx.x, lane = tid & 31, wid = tid >> 5;
    const int wm = wid & 3, wn = wid >> 2;
    const size_t rowBase = (size_t)blockIdx.y * 128;
    const int colBase = blockIdx.x * 128;
    const int nch = K / 64;

    float acc[2][8][4];
#pragma unroll
    for (int i = 0; i < 2; i++)
#pragma unroll
        for (int j = 0; j < 8; j++)
#pragma unroll
            for (int q = 0; q < 4; q++) acc[i][j][q] = 0.f;

#pragma unroll
    for (int p = 0; p < 2; p++) {
        bf16* nb = sm + p * P1_BUF;
        int k0 = p * 64;
        ld_sw<128, 8>(nb + P1_AH, Ah, rowBase, K, k0, tid);
        ld_sw<128, 8>(nb + P1_AL, Al, rowBase, K, k0, tid);
        ld_sw<128, 8>(nb + P1_BH, Bh, (size_t)colBase, K, k0, tid);
        ld_sw<128, 8>(nb + P1_BL, Bl, (size_t)colBase, K, k0, tid);
        CP_COMMIT();
    }

    for (int kc = 0; kc < nch; kc++) {
        if (kc < nch - 1) { CP_WAIT(1); } else { CP_WAIT(0); }
        __syncthreads();
        if (kc + 2 < nch) {
            bf16* nb = sm + ((kc + 2) % 3) * P1_BUF;
            int k0 = (kc + 2) * 64;
            ld_sw<128, 8>(nb + P1_AH, Ah, rowBase, K, k0, tid);
            ld_sw<128, 8>(nb + P1_AL, Al, rowBase, K, k0, tid);
            ld_sw<128, 8>(nb + P1_BH, Bh, (size_t)colBase, K, k0, tid);
            ld_sw<128, 8>(nb + P1_BL, Bl, (size_t)colBase, K, k0, tid);
            CP_COMMIT();
        }
        bf16* cb = sm + (kc % 3) * P1_BUF;
#pragma unroll
        for (int ks = 0; ks < 4; ks++) {
            int ko = ks * 16;
            uint32_t ah[2][4], al[2][4];
#pragma unroll
            for (int mf = 0; mf < 2; mf++) {
                ldsm4_s(ah[mf], cb + P1_AH, 64, wm * 32 + mf * 16, ko, lane);
                ldsm4_s(al[mf], cb + P1_AL, 64, wm * 32 + mf * 16, ko, lane);
            }
#pragma unroll
            for (int np = 0; np < 4; np++) {
                uint32_t bh4[4], bl4[4];
                ldsm4_n16(bh4, cb + P1_BH, 64, wn * 64 + np * 16, ko, lane);
                ldsm4_n16(bl4, cb + P1_BL, 64, wn * 64 + np * 16, ko, lane);
#pragma unroll
                for (int s = 0; s < 2; s++) {
#pragma unroll
                    for (int mf = 0; mf < 2; mf++) {
                        hmma(acc[mf][np * 2 + s], ah[mf], bh4 + 2 * s);
                        hmma(acc[mf][np * 2 + s], ah[mf], bl4 + 2 * s);
                        hmma(acc[mf][np * 2 + s], al[mf], bh4 + 2 * s);
                    }
                }
            }
        }
    }

#pragma unroll
    for (int mf = 0; mf < 2; mf++) {
#pragma unroll
        for (int nf = 0; nf < 8; nf++) {
            int cg = colBase + wn * 64 + nf * 8 + (lane & 3) * 2;
            float b0 = bias[cg], b1 = bias[cg + 1];
#pragma unroll
            for (int half = 0; half < 2; half++) {
                size_t rg = rowBase + wm * 32 + mf * 16 + (lane >> 2) + half * 8;
                float v0 = acc[mf][nf][half * 2] + b0;
                float v1 = acc[mf][nf][half * 2 + 1] + b1;
                if (relu_split) {
                    v0 = fmaxf(v0, 0.f);
                    v1 = fmaxf(v1, 0.f);
                    __nv_bfloat162 hv, lv;
                    hv.x = __float2bfloat16(v0);
                    hv.y = __float2bfloat16(v1);
                    lv.x = __float2bfloat16(v0 - __bfloat162float(hv.x));
                    lv.y = __float2bfloat16(v1 - __bfloat162float(hv.y));
                    *(__nv_bfloat162*)&outH[rg * N + cg] = hv;
                    *(__nv_bfloat162*)&outL[rg * N + cg] = lv;
                } else {
                    *(float2*)&outF[rg * N + cg] = make_float2(v0, v1);
                }
            }
        }
    }
}

// ---------------- persistent recurrence: 8 groups x 16 CTAs -----------------
// R15 structure; change: phase B single-sync (4 syncs, issue-after-sync).
#define RW_H 0
#define RW_L 32768
#define RD 65536
#define PB_AH 0
#define PB_AL 4096
#define PB_WH 8192
#define PB_WL 16384
#define PB_STAGE 24576
#define PA_ST 16384
#define R_SMEM ((65536 + 2 * 24576) * 2)

__global__ __launch_bounds__(256) void recurrence(
    const float* __restrict__ b1h, const float* __restrict__ b2h,
    const int* __restrict__ lens, float* __restrict__ out)
{
    extern __shared__ bf16 sm[];
    bf16* smWH = sm + RW_H;
    bf16* smWL = sm + RW_L;
    const int tid = threadIdx.x, lane = tid & 31, wid = tid >> 5;
    const int wm = wid & 1, wn = wid >> 1;  // 2m x 4n warps
    const int cta = blockIdx.x;
    const int grp = cta >> 4;
    const int slot = cta & 15;
    const size_t rbase = (size_t)grp * 32;
    const int cbaseA = slot * 32;
    const int cbaseB = slot * 64;

    const unsigned baseH = g_fh[grp][slot * 32];
    const unsigned baseI = g_fi[grp][slot * 32];

    // zero h state by COLUMN ownership
    for (int i = tid; i < 32 * 32; i += 256) {
        int r = i >> 5, c = (i & 31) * 2;
        size_t j = (rbase + r) * H_ + cbaseB + c;
        *(__nv_bfloat162*)&g_hh[j] = __nv_bfloat162{__float2bfloat16(0.f), __float2bfloat16(0.f)};
        *(__nv_bfloat162*)&g_hl[j] = __nv_bfloat162{__float2bfloat16(0.f), __float2bfloat16(0.f)};
    }
    __syncthreads();
    if (tid == 0) publish(&g_fh[grp][slot * 32], baseH + 1);

    // resident phase-A weights
    for (int i = tid; i < 32 * 128; i += 256) {
        int r = i >> 7, c = i & 127;
        int d = r * 1024 + ((c ^ (r & 7)) << 3);
        *(uint4*)(smWH + d) = *(const uint4*)&g_w1hTh[(size_t)(cbaseA + r) * H_ + c * 8];
        *(uint4*)(smWL + d) = *(const uint4*)&g_w1hTl[(size_t)(cbaseA + r) * H_ + c * 8];
    }
    __syncthreads();

    const size_t rg0 = rbase + wm * 16 + (lane >> 2);
    const size_t rg1 = rg0 + 8;
    const int len0 = lens[rg0], len1 = lens[rg1];
    const int cgA = cbaseA + wn * 8 + (lane & 3) * 2;
    const float pb1_0 = b1h[cgA], pb1_1 = b1h[cgA + 1];
    float pb2[2][2];
#pragma unroll
    for (int nf = 0; nf < 2; nf++) {
        int cg = cbaseB + wn * 16 + nf * 8 + (lane & 3) * 2;
        pb2[nf][0] = b2h[cg];
        pb2[nf][1] = b2h[cg + 1];
    }
    float h_prev[2][4];
#pragma unroll
    for (int nf = 0; nf < 2; nf++)
#pragma unroll
        for (int q = 0; q < 4; q++) h_prev[nf][q] = 0.f;

    for (int t = 0; t < S_; t++) {
        const unsigned tgtH = baseH + (unsigned)t + 1;
        const unsigned tgtI = baseI + (unsigned)t + 1;
        const int par = t & 1;
        const bf16* ihr = g_ih[par];
        const bf16* ilr = g_il[par];

        // xh prefetch (flag-independent)
        float2 xv[2][2];
#pragma unroll
        for (int nf = 0; nf < 2; nf++) {
            int cg = cbaseB + wn * 16 + nf * 8 + (lane & 3) * 2;
            xv[nf][0] = *(const float2*)&g_xh[(rg0 * S_ + t) * H_ + cg];
            xv[nf][1] = *(const float2*)&g_xh[(rg1 * S_ + t) * H_ + cg];
        }

        // ---- phase A prologue: fill 2 of 3 stages (K-chunks of 256) ----
#pragma unroll
        for (int p = 0; p < 2; p++) {
            wait_flags(g_fh[grp] + 4 * p * 32, 4, tgtH, lane);
            bf16* hs = sm + RD + p * PA_ST;
            ld_sw<32, 32>(hs, g_hh, rbase, H_, p * 256, tid);
            ld_sw<32, 32>(hs + 8192, g_hl, rbase, H_, p * 256, tid);
            CP_COMMIT();
        }

        // ================= phase A (4 chunks of K=256, ONE sync each) ======
        float accA[3][4];
#pragma unroll
        for (int i = 0; i < 3; i++)
#pragma unroll
            for (int q = 0; q < 4; q++) accA[i][q] = 0.f;

#pragma unroll
        for (int kc = 0; kc < 4; kc++) {
            if (kc < 3) { CP_WAIT(1); } else { CP_WAIT(0); }
            __syncthreads();
            if (kc < 2) {
                int c = kc + 2;
                wait_flags(g_fh[grp] + 4 * c * 32, 4, tgtH, lane);
                bf16* ns = sm + RD + (c % 3) * PA_ST;
                ld_sw<32, 32>(ns, g_hh, rbase, H_, c * 256, tid);
                ld_sw<32, 32>(ns + 8192, g_hl, rbase, H_, c * 256, tid);
                CP_COMMIT();
            }
            bf16* hs = sm + RD + (kc % 3) * PA_ST;
#pragma unroll
            for (int ks = 0; ks < 16; ks++) {
                int ko = ks * 16;
                uint32_t ah[4], al[4], bh[2], bl[2];
                ldsm4_s(ah, hs, 256, wm * 16, ko, lane);
                ldsm4_s(al, hs + 8192, 256, wm * 16, ko, lane);
                ldsm2_s(bh, smWH, 1024, wn * 8, kc * 256 + ko, lane);
                ldsm2_s(bl, smWL, 1024, wn * 8, kc * 256 + ko, lane);
                hmma(accA[0], ah, bh);
                hmma(accA[1], ah, bl);
                hmma(accA[2], al, bh);
            }
        }

        // ---- epilogue A: relu + split -> inter (buffer t&1) ----
#pragma unroll
        for (int half = 0; half < 2; half++) {
            size_t rg = (half == 0) ? rg0 : rg1;
            float v0 = fmaxf(accA[0][half * 2] + accA[1][half * 2] +
                             accA[2][half * 2] + pb1_0, 0.f);
            float v1 = fmaxf(accA[0][half * 2 + 1] + accA[1][half * 2 + 1] +
                             accA[2][half * 2 + 1] + pb1_1, 0.f);
            __nv_bfloat162 hv, lv;
            hv.x = __float2bfloat16(v0);
            hv.y = __float2bfloat16(v1);
            lv.x = __float2bfloat16(v0 - __bfloat162float(hv.x));
            lv.y = __float2bfloat16(v1 - __bfloat162float(hv.y));
            *(__nv_bfloat162*)&g_ih[par][rg * HH_ + cgA] = hv;
            *(__nv_bfloat162*)&g_il[par][rg * HH_ + cgA] = lv;
        }
        __syncthreads();   // PA stages free + inter stores done
        if (tid == 0) publish(&g_fi[grp][slot * 32], tgtI);

        // ---- phase B prologue: W0, W1 (flag-independent), then I0, I1 ----
        ld_sw<64, 16>(sm + RD + PB_WH, g_w2hTh, (size_t)cbaseB, HH_, 0, tid);
        ld_sw<64, 16>(sm + RD + PB_WL, g_w2hTl, (size_t)cbaseB, HH_, 0, tid);
        CP_COMMIT();   // C1 = W0
        ld_sw<64, 16>(sm + RD + PB_STAGE + PB_WH, g_w2hTh, (size_t)cbaseB, HH_, 128, tid);
        ld_sw<64, 16>(sm + RD + PB_STAGE + PB_WL, g_w2hTl, (size_t)cbaseB, HH_, 128, tid);
        CP_COMMIT();   // C2 = W1
        wait_flags(g_fi[grp], 4, tgtI, lane);
        ld_sw<32, 16>(sm + RD + PB_AH, ihr, rbase, HH_, 0, tid);
        ld_sw<32, 16>(sm + RD + PB_AL, ilr, rbase, HH_, 0, tid);
        CP_COMMIT();   // C3 = I0
        wait_flags(g_fi[grp] + 4 * 32, 4, tgtI, lane);
        ld_sw<32, 16>(sm + RD + PB_STAGE + PB_AH, ihr, rbase, HH_, 128, tid);
        ld_sw<32, 16>(sm + RD + PB_STAGE + PB_AL, ilr, rbase, HH_, 128, tid);
        CP_COMMIT();   // C4 = I1

        // ================= phase B (4 chunks of K=128, ONE sync each) ======
        float accB[2][3][4];
#pragma unroll
        for (int nf = 0; nf < 2; nf++)
#pragma unroll
            for (int i = 0; i < 3; i++)
#pragma unroll
                for (int q = 0; q < 4; q++) accB[nf][i][q] = 0.f;

#pragma unroll
        for (int kc = 0; kc < 4; kc++) {
            if (kc == 0) { CP_WAIT(1); } else { CP_WAIT(0); }
            __syncthreads();
            if (kc >= 1 && kc < 3) {
                // issue chunk kc+1 into stage (kc+1)&1, freed at iteration kc-1
                int k0 = (kc + 1) * 128;
                wait_flags(g_fi[grp] + (4 * (kc + 1)) * 32, 4, tgtI, lane);
                bf16* ns = sm + RD + ((kc + 1) & 1) * PB_STAGE;
                ld_sw<32, 16>(ns + PB_AH, ihr, rbase, HH_, k0, tid);
                ld_sw<32, 16>(ns + PB_AL, ilr, rbase, HH_, k0, tid);
                ld_sw<64, 16>(ns + PB_WH, g_w2hTh, (size_t)cbaseB, HH_, k0, tid);
                ld_sw<64, 16>(ns + PB_WL, g_w2hTl, (size_t)cbaseB, HH_, k0, tid);
                CP_COMMIT();
            }
            bf16* cb = sm + RD + (kc & 1) * PB_STAGE;
#pragma unroll
            for (int ks = 0; ks < 8; ks++) {
                int ko = ks * 16;
                uint32_t ah[4], al[4], bh4[4], bl4[4];
                ldsm4_s(ah, cb + PB_AH, 128, wm * 16, ko, lane);
                ldsm4_s(al, cb + PB_AL, 128, wm * 16, ko, lane);
                ldsm4_n16(bh4, cb + PB_WH, 128, wn * 16, ko, lane);
                ldsm4_n16(bl4, cb + PB_WL, 128, wn * 16, ko, lane);
#pragma unroll
                for (int nf = 0; nf < 2; nf++) {
                    hmma(accB[nf][0], ah, bh4 + 2 * nf);
                    hmma(accB[nf][1], ah, bl4 + 2 * nf);
                    hmma(accB[nf][2], al, bh4 + 2 * nf);
                }
            }
        }

        // ---- epilogue B: compute + h-state stores FIRST, publish, then out --
        float res[2][2][2];
#pragma unroll
        for (int nf = 0; nf < 2; nf++) {
            int cg = cbaseB + wn * 16 + nf * 8 + (lane & 3) * 2;
#pragma unroll
            for (int half = 0; half < 2; half++) {
                bool on = t < ((half == 0) ? len0 : len1);
                size_t rg = (half == 0) ? rg0 : rg1;
                float v0, v1;
                if (on) {
                    float s0 = accB[nf][0][half * 2] + accB[nf][1][half * 2] +
                               accB[nf][2][half * 2];
                    float s1 = accB[nf][0][half * 2 + 1] + accB[nf][1][half * 2 + 1] +
                               accB[nf][2][half * 2 + 1];
                    v0 = fast_tanh(xv[nf][half].x + s0 + pb2[nf][0]);
                    v1 = fast_tanh(xv[nf][half].y + s1 + pb2[nf][1]);
                    h_prev[nf][half * 2] = v0;
                    h_prev[nf][half * 2 + 1] = v1;
                    __nv_bfloat162 hv, lv;
                    hv.x = __float2bfloat16(v0);
                    hv.y = __float2bfloat16(v1);
                    lv.x = __float2bfloat16(v0 - __bfloat162float(hv.x));
                    lv.y = __float2bfloat16(v1 - __bfloat162float(hv.y));
                    *(__nv_bfloat162*)&g_hh[rg * H_ + cg] = hv;
                    *(__nv_bfloat162*)&g_hl[rg * H_ + cg] = lv;
                } else {
                    v0 = h_prev[nf][half * 2];
                    v1 = h_prev[nf][half * 2 + 1];
                }
                res[nf][half][0] = v0;
                res[nf][half][1] = v1;
            }
        }
        __syncthreads();
        if (tid == 0) publish(&g_fh[grp][slot * 32], baseH + (unsigned)t + 2);
        // out writes off the critical path, streaming
#pragma unroll
        for (int nf = 0; nf < 2; nf++) {
            int cg = cbaseB + wn * 16 + nf * 8 + (lane & 3) * 2;
#pragma unroll
            for (int half = 0; half < 2; half++) {
                size_t rg = (half == 0) ? rg0 : rg1;
                __stcs((float2*)&out[(rg * S_ + t) * H_ + cg],
                       make_float2(res[nf][half][0], res[nf][half][1]));
            }
        }
    }
}

// ---------------- launcher --------------------------------------------------
extern "C" void kernel_launch(void* const* d_in, const int* in_sizes, int n_in,
                              void* d_out, int out_size) {
    const float* seq = (const float*)d_in[0];
    const int* lens  = (const int*)d_in[1];
    const float* w1x = (const float*)d_in[2];
    const float* b1x = (const float*)d_in[3];
    const float* w2x = (const float*)d_in[4];
    const float* b2x = (const float*)d_in[5];
    const float* w1h = (const float*)d_in[6];
    const float* b1h = (const float*)d_in[7];
    const float* w2h = (const float*)d_in[8];
    const float* b2h = (const float*)d_in[9];
    float* out = (float*)d_out;

    bf16 *seqh, *seql, *tmph, *tmpl;
    bf16 *w1xh, *w1xl, *w2xh, *w2xl, *w1hh, *w1hl, *w2hh, *w2hl;
    float* xh;
    cudaGetSymbolAddress((void**)&seqh, g_seqh);
    cudaGetSymbolAddress((void**)&seql, g_seql);
    cudaGetSymbolAddress((void**)&tmph, g_tmph);
    cudaGetSymbolAddress((void**)&tmpl, g_tmpl);
    cudaGetSymbolAddress((void**)&xh, g_xh);
    cudaGetSymbolAddress((void**)&w1xh, g_w1xTh);
    cudaGetSymbolAddress((void**)&w1xl, g_w1xTl);
    cudaGetSymbolAddress((void**)&w2xh, g_w2xTh);
    cudaGetSymbolAddress((void**)&w2xl, g_w2xTl);
    cudaGetSymbolAddress((void**)&w1hh, g_w1hTh);
    cudaGetSymbolAddress((void**)&w1hl, g_w1hTl);
    cudaGetSymbolAddress((void**)&w2hh, g_w2hTh);
    cudaGetSymbolAddress((void**)&w2hl, g_w2hTl);

    cudaFuncSetAttribute(ff_mma, cudaFuncAttributeMaxDynamicSharedMemorySize, P1_SMEM);
    cudaFuncSetAttribute(recurrence, cudaFuncAttributeMaxDynamicSharedMemorySize, R_SMEM);

    size_t nseq = (size_t)MTOK * E_;
    split_kernel<<<(unsigned)((nseq + 255) / 256), 256>>>(seq, seqh, seql, nseq);
    transpose_split<<<(E_ * HH_ + 255) / 256, 256>>>(w1x, w1xh, w1xl, E_, HH_);
    transpose_split<<<(HH_ * H_ + 255) / 256, 256>>>(w2x, w2xh, w2xl, HH_, H_);
    transpose_split<<<(H_ * HH_ + 255) / 256, 256>>>(w1h, w1hh, w1hl, H_, HH_);
    transpose_split<<<(HH_ * H_ + 255) / 256, 256>>>(w2h, w2hh, w2hl, HH_, H_);

    ff_mma<<<dim3(HH_ / 128, MTOK / 128), 256, P1_SMEM>>>(
        seqh, seql, w1xh, w1xl, b1x, nullptr, tmph, tmpl, E_, HH_, 1);
    ff_mma<<<dim3(H_ / 128, MTOK / 128), 256, P1_SMEM>>>(
        tmph, tmpl, w2xh, w2xl, b2x, xh, nullptr, nullptr, HH_, H_, 0);

    recurrence<<<128, 256, R_SMEM>>>(b1h, b2h, lens, out);
}